// round 15
// baseline (speedup 1.0000x reference)
#include <cuda_runtime.h>
#include <cuda_fp16.h>
#include <math.h>

// ---------------- problem constants ----------------
#define Bv   4
#define Tv   1024
#define Dv   2048
#define Hv   32
#define DHv  64
#define HKv  8
#define Rv   32
#define ROv  1024
#define RFv  1024
#define Iv   5632
#define BT   (Bv*Tv)     // 4096

// ---------------- scratch ----------------
__device__ __half g_h1 [BT*Dv];
__device__ __half g_qr [BT*(Hv*Rv)];
__device__ __half g_kr [BT*(HKv*Rv)];
__device__ __half g_vr [BT*(HKv*Rv)];
__device__ __half g_q  [Bv*Hv*Tv*DHv];
__device__ __half g_k  [Bv*HKv*Tv*DHv];
__device__ __half g_v  [Bv*HKv*Tv*DHv];
__device__ __half g_ctx[BT*Dv];
__device__ __half g_or [BT*ROv];
__device__ float  g_x1 [BT*Dv];
__device__ __half g_h2 [BT*Dv];
__device__ __half g_gr [BT*RFv];
__device__ __half g_ur [BT*RFv];
__device__ __half g_g  [BT*Iv];
__device__ __half g_ff [BT*Iv];
__device__ __half g_dr [BT*RFv];
__device__ float  g_ropec[Tv*32];
__device__ float  g_ropes[Tv*32];
__device__ __half g_qush[Hv*DHv*Rv];
__device__ __half g_kush[HKv*DHv*Rv];
__device__ __half g_vush[HKv*DHv*Rv];
// converted (half) weights, concatenated; offsets in elements
#define W_QV   0
#define W_KV   2097152
#define W_VV   2621440
#define W_OV   3145728
#define W_OUS  5242880
#define W_GV   7340032
#define W_UV   9437184
#define W_GUS  11534336
#define W_UUS  17301504
#define W_DV   23068672
#define W_DUS  28835840
#define W_TOT  30932992
#define NW1BLK (W_OV/4096)
#define NW2BLK ((W_TOT-W_OV)/4096)
#define NROPE  (Tv*32/256)
#define NQUS   (Hv*DHv*Rv/4096)
#define NKUS   (HKv*DHv*Rv/4096)
__device__ __half g_wts[W_TOT];

// ---------------- helpers ----------------
__device__ __forceinline__ uint2 pack4h(float4 v) {
    __half2 a = __floats2half2_rn(v.x, v.y);
    __half2 b = __floats2half2_rn(v.z, v.w);
    uint2 r;
    r.x = *(unsigned*)&a;
    r.y = *(unsigned*)&b;
    return r;
}
__device__ __forceinline__ float ex2f(float x) {
    float r;
    asm("ex2.approx.ftz.f32 %0, %1;" : "=f"(r) : "f"(x));
    return r;
}
#define LOG2E 1.4426950408889634f

// ---------------- prep part 1: QKV weights + rms1 + rope table + Us->half ----------------
__global__ void __launch_bounds__(256) prep_qkv(
    __half* __restrict__ dst,
    const float* __restrict__ s0, const float* __restrict__ s1, const float* __restrict__ s2,
    const float* __restrict__ x, const float* __restrict__ ln1_w, __half* __restrict__ h1,
    float* __restrict__ rc, float* __restrict__ rs,
    const float* __restrict__ qUs, const float* __restrict__ kUs, const float* __restrict__ vUs,
    __half* __restrict__ qUh, __half* __restrict__ kUh, __half* __restrict__ vUh)
{
    int bx = blockIdx.x;
    int tid = threadIdx.x;
    if (bx < NW1BLK) {
        long i = ((long)bx * 256 + tid) * 16;
        const float* src; long base;
        if (i < W_KV)      { src = s0; base = W_QV; }
        else if (i < W_VV) { src = s1; base = W_KV; }
        else               { src = s2; base = W_VV; }
        const float4* sp = (const float4*)(src + (i - base));
        float4 v0 = sp[0], v1 = sp[1], v2 = sp[2], v3 = sp[3];
        uint2 p0 = pack4h(v0), p1 = pack4h(v1), p2 = pack4h(v2), p3 = pack4h(v3);
        uint4 o0 = { p0.x, p0.y, p1.x, p1.y };
        uint4 o1 = { p2.x, p2.y, p3.x, p3.y };
        *(uint4*)(dst + i)     = o0;
        *(uint4*)(dst + i + 8) = o1;
    } else if (bx < NW1BLK + BT) {
        int row = bx - NW1BLK;
        const float4* xr = (const float4*)(x + (size_t)row * Dv);
        float4 v0 = xr[tid];
        float4 v1 = xr[tid + 256];
        float ss = v0.x*v0.x + v0.y*v0.y + v0.z*v0.z + v0.w*v0.w
                 + v1.x*v1.x + v1.y*v1.y + v1.z*v1.z + v1.w*v1.w;
        #pragma unroll
        for (int o = 16; o; o >>= 1) ss += __shfl_xor_sync(0xffffffffu, ss, o);
        __shared__ float red[8];
        if ((tid & 31) == 0) red[tid >> 5] = ss;
        __syncthreads();
        float tot = 0.f;
        #pragma unroll
        for (int i = 0; i < 8; i++) tot += red[i];
        float inv = rsqrtf(tot * (1.0f / Dv) + 1e-5f);
        const float4* wr = (const float4*)ln1_w;
        float4 w0 = wr[tid], w1 = wr[tid + 256];
        float4 o0 = { v0.x*inv*w0.x, v0.y*inv*w0.y, v0.z*inv*w0.z, v0.w*inv*w0.w };
        float4 o1 = { v1.x*inv*w1.x, v1.y*inv*w1.y, v1.z*inv*w1.z, v1.w*inv*w1.w };
        __half* orow = h1 + (size_t)row * Dv;
        *(uint2*)(orow + tid * 4)         = pack4h(o0);
        *(uint2*)(orow + (tid + 256) * 4) = pack4h(o1);
    } else if (bx < NW1BLK + BT + NROPE) {
        int idx = (bx - NW1BLK - BT) * 256 + tid;
        int t = idx >> 5, d = idx & 31;
        float invf = expf(-0.28782313662425572f * (float)d);
        float ang = (float)t * invf;
        rc[idx] = cosf(ang);
        rs[idx] = sinf(ang);
    } else {
        int ub = bx - NW1BLK - BT - NROPE;
        const float* src; __half* dh;
        long i;
        if (ub < NQUS)            { src = qUs; dh = qUh; i = ((long)ub * 256 + tid) * 16; }
        else if (ub < NQUS+NKUS)  { src = kUs; dh = kUh; i = ((long)(ub-NQUS) * 256 + tid) * 16; }
        else                      { src = vUs; dh = vUh; i = ((long)(ub-NQUS-NKUS) * 256 + tid) * 16; }
        const float4* sp = (const float4*)(src + i);
        float4 v0 = sp[0], v1 = sp[1], v2 = sp[2], v3 = sp[3];
        uint2 p0 = pack4h(v0), p1 = pack4h(v1), p2 = pack4h(v2), p3 = pack4h(v3);
        uint4 o0 = { p0.x, p0.y, p1.x, p1.y };
        uint4 o1 = { p2.x, p2.y, p3.x, p3.y };
        *(uint4*)(dh + i)     = o0;
        *(uint4*)(dh + i + 8) = o1;
    }
}

// ---------------- prep part 2: O/G/U/D weights (side stream) ----------------
__global__ void __launch_bounds__(256) prep_mlp(
    __half* __restrict__ dst,
    const float* __restrict__ s3, const float* __restrict__ s4, const float* __restrict__ s5,
    const float* __restrict__ s6, const float* __restrict__ s7, const float* __restrict__ s8,
    const float* __restrict__ s9, const float* __restrict__ s10)
{
    long i = W_OV + ((long)blockIdx.x * 256 + threadIdx.x) * 16;
    const float* src; long base;
    if (i < W_GUS) {
        if (i < W_OUS)       { src = s3; base = W_OV; }
        else if (i < W_GV)   { src = s4; base = W_OUS; }
        else if (i < W_UV)   { src = s5; base = W_GV; }
        else                 { src = s6; base = W_UV; }
    } else {
        if (i < W_UUS)       { src = s7; base = W_GUS; }
        else if (i < W_DV)   { src = s8; base = W_UUS; }
        else if (i < W_DUS)  { src = s9; base = W_DV; }
        else                 { src = s10; base = W_DUS; }
    }
    const float4* sp = (const float4*)(src + (i - base));
    float4 v0 = sp[0], v1 = sp[1], v2 = sp[2], v3 = sp[3];
    uint2 p0 = pack4h(v0), p1 = pack4h(v1), p2 = pack4h(v2), p3 = pack4h(v3);
    uint4 o0 = { p0.x, p0.y, p1.x, p1.y };
    uint4 o1 = { p2.x, p2.y, p3.x, p3.y };
    *(uint4*)(dst + i)     = o0;
    *(uint4*)(dst + i + 8) = o1;
}

// ---------------- RMSNorm (fp32 in, fp16 out) ----------------
__global__ void __launch_bounds__(256) rms_kernel(const float* __restrict__ x,
                                                  const float* __restrict__ w,
                                                  __half* __restrict__ out)
{
    int row = blockIdx.x;
    int tid = threadIdx.x;
    const float4* xr = (const float4*)(x + (size_t)row * Dv);
    float4 v0 = xr[tid];
    float4 v1 = xr[tid + 256];
    float ss = v0.x*v0.x + v0.y*v0.y + v0.z*v0.z + v0.w*v0.w
             + v1.x*v1.x + v1.y*v1.y + v1.z*v1.z + v1.w*v1.w;
    #pragma unroll
    for (int o = 16; o; o >>= 1) ss += __shfl_xor_sync(0xffffffffu, ss, o);
    __shared__ float red[8];
    if ((tid & 31) == 0) red[tid >> 5] = ss;
    __syncthreads();
    float tot = 0.f;
    #pragma unroll
    for (int i = 0; i < 8; i++) tot += red[i];
    float inv = rsqrtf(tot * (1.0f / Dv) + 1e-5f);
    const float4* wr = (const float4*)w;
    float4 w0 = wr[tid], w1 = wr[tid + 256];
    float4 o0 = { v0.x*inv*w0.x, v0.y*inv*w0.y, v0.z*inv*w0.z, v0.w*inv*w0.w };
    float4 o1 = { v1.x*inv*w1.x, v1.y*inv*w1.y, v1.z*inv*w1.z, v1.w*inv*w1.w };
    __half* orow = out + (size_t)row * Dv;
    *(uint2*)(orow + tid * 4)         = pack4h(o0);
    *(uint2*)(orow + (tid + 256) * 4) = pack4h(o1);
}

// ---------------- fp16 tensor-core GEMM: CTA 128x256, warp 64x64, 3-stage ----------------
#define STAGES 3
#define STG_BYTES 49152u     // 16KB A + 32KB B per stage

#define CP_ASYNC16(dst, src) asm volatile("cp.async.cg.shared.global [%0], [%1], 16;\n" :: "r"(dst), "l"(src))
#define CP_COMMIT() asm volatile("cp.async.commit_group;\n" ::)
#define CP_WAIT(n)  asm volatile("cp.async.wait_group %0;\n" :: "n"(n))

#define LDSM4(r0, r1, r2, r3, addr) \
    asm volatile("ldmatrix.sync.aligned.m8n8.x4.shared.b16 {%0,%1,%2,%3}, [%4];" \
        : "=r"(r0), "=r"(r1), "=r"(r2), "=r"(r3) : "r"(addr))

#define LDSM4T(r0, r1, r2, r3, addr) \
    asm volatile("ldmatrix.sync.aligned.m8n8.x4.trans.shared.b16 {%0,%1,%2,%3}, [%4];" \
        : "=r"(r0), "=r"(r1), "=r"(r2), "=r"(r3) : "r"(addr))

#define MMA_F16(d, a, b) \
    asm volatile("mma.sync.aligned.m16n8k16.row.col.f32.f16.f16.f32 " \
        "{%0,%1,%2,%3}, {%4,%5,%6,%7}, {%8,%9}, {%0,%1,%2,%3};" \
        : "+f"(d[0]), "+f"(d[1]), "+f"(d[2]), "+f"(d[3]) \
        : "r"(a[0]), "r"(a[1]), "r"(a[2]), "r"(a[3]), "r"(b[0]), "r"(b[1]))

__global__ void __launch_bounds__(256, 1) gemm_h(
    const __half* __restrict__ A, int K, int mode, const void* __restrict__ aux,
    const __half* __restrict__ B0, void* __restrict__ C0, int N0, int nb0,
    const __half* __restrict__ B1, void* __restrict__ C1, int N1, int nb1,
    const __half* __restrict__ B2, void* __restrict__ C2, int N2, int nb2)
{
    extern __shared__ __half smem[];
    unsigned sbase = (unsigned)__cvta_generic_to_shared(smem);

    int bx = blockIdx.x;
    const __half* Bw; void* C; int N; int bnb;
    if (bx < nb0)            { Bw = B0; C = C0; N = N0; bnb = bx; }
    else if (bx < nb0 + nb1) { Bw = B1; C = C1; N = N1; bnb = bx - nb0; }
    else                     { Bw = B2; C = C2; N = N2; bnb = bx - nb0 - nb1; }

    int tid  = threadIdx.x;
    int bm = blockIdx.y * 128;
    int bn = bnb * 256;
    int lane = tid & 31, warp = tid >> 5;
    int wm = warp & 1, wn = warp >> 1;      // 2 x 4 warp grid, warp tile 64x64
    int g  = lane >> 2, tig = lane & 3;
    int t4 = lane >> 3;

    // cp.async: 12 x 16B per thread per k-tile (A 128 rows + B 256 rows, 8 chunks each)
    unsigned dstoff[12];
    const __half* srcp[12];
    #pragma unroll
    for (int i = 0; i < 12; i++) {
        int lin = tid + i * 256;            // 0..3071
        int row = lin >> 3, c = lin & 7;
        if (row < 128) {
            dstoff[i] = (unsigned)(row * 128 + ((c ^ (row & 7)) << 4));
            srcp[i] = A + (size_t)(bm + row) * K + c * 8;
        } else {
            int rb = row - 128;
            dstoff[i] = (unsigned)(16384 + rb * 128 + ((c ^ (rb & 7)) << 4));
            srcp[i] = Bw + (size_t)(bn + rb) * K + c * 8;
        }
    }

    // fragment offsets
    unsigned aoff[4][4], boff[4][4];
    #pragma unroll
    for (int mi = 0; mi < 4; mi++) {
        int row = wm * 64 + mi * 16 + (lane & 7) + (t4 & 1) * 8;
        #pragma unroll
        for (int ks = 0; ks < 4; ks++) {
            int chunk = 2 * ks + (t4 >> 1);
            aoff[mi][ks] = (unsigned)(row * 128 + ((chunk ^ (row & 7)) << 4));
        }
    }
    #pragma unroll
    for (int np = 0; np < 4; np++) {
        int row = wn * 64 + np * 16 + (lane & 7) + (t4 >> 1) * 8;
        #pragma unroll
        for (int ks = 0; ks < 4; ks++) {
            int chunk = 2 * ks + (t4 & 1);
            boff[np][ks] = (unsigned)(16384 + row * 128 + ((chunk ^ (row & 7)) << 4));
        }
    }

    float acc[4][8][4];
    #pragma unroll
    for (int mi = 0; mi < 4; mi++)
        #pragma unroll
        for (int ni = 0; ni < 8; ni++)
            #pragma unroll
            for (int q = 0; q < 4; q++) acc[mi][ni][q] = 0.f;

    const int NT = K >> 6;

    #pragma unroll
    for (int s = 0; s < STAGES - 1; s++) {
        unsigned db = sbase + (unsigned)s * STG_BYTES;
        #pragma unroll
        for (int i = 0; i < 12; i++)
            CP_ASYNC16(db + dstoff[i], srcp[i] + (size_t)s * 64);
        CP_COMMIT();
    }

    for (int kt = 0; kt < NT; kt++) {
        int st = kt % STAGES;
        CP_WAIT(STAGES - 2);
        __syncthreads();

        int pf = kt + STAGES - 1;
        if (pf < NT) {
            unsigned db = sbase + (unsigned)(pf % STAGES) * STG_BYTES;
            #pragma unroll
            for (int i = 0; i < 12; i++)
                CP_ASYNC16(db + dstoff[i], srcp[i] + (size_t)pf * 64);
        }
        CP_COMMIT();

        unsigned SB = sbase + (unsigned)st * STG_BYTES;

        #pragma unroll
        for (int ks = 0; ks < 4; ks++) {
            unsigned af[4][4];
            #pragma unroll
            for (int mi = 0; mi < 4; mi++)
                LDSM4(af[mi][0], af[mi][1], af[mi][2], af[mi][3], SB + aoff[mi][ks]);
            unsigned bf[8][2];
            #pragma unroll
            for (int np = 0; np < 4; np++)
                LDSM4(bf[2*np][0], bf[2*np][1], bf[2*np+1][0], bf[2*np+1][1],
                      SB + boff[np][ks]);
            #pragma unroll
            for (int mi = 0; mi < 4; mi++)
                #pragma unroll
                for (int ni = 0; ni < 8; ni++)
                    MMA_F16(acc[mi][ni], af[mi], bf[ni]);
        }
    }

    // epilogue
    #pragma unroll
    for (int mi = 0; mi < 4; mi++) {
        int row0 = bm + wm * 64 + mi * 16 + g;
        #pragma unroll
        for (int half = 0; half < 2; half++) {
            int row = row0 + half * 8;
            size_t rowoff = (size_t)row * N;
            #pragma unroll
            for (int ni = 0; ni < 8; ni++) {
                int col = bn + wn * 64 + ni * 8 + 2 * tig;
                size_t idx = rowoff + col;
                float vx = acc[mi][ni][half * 2 + 0];
                float vy = acc[mi][ni][half * 2 + 1];
                if (mode == 1) {
                    float2 rsd = *(const float2*)((const float*)aux + idx);
                    vx += rsd.x; vy += rsd.y;
                    float2 o = { vx, vy };
                    *(float2*)((float*)C + idx) = o;
                } else {
                    if (mode == 2) {
                        __half2 gh = *(const __half2*)((const __half*)aux + idx);
                        float2 gf = __half22float2(gh);
                        vx *= gf.x / (1.f + __expf(-gf.x));
                        vy *= gf.y / (1.f + __expf(-gf.y));
                    }
                    __half2 o = __floats2half2_rn(vx, vy);
                    *(__half2*)((__half*)C + idx) = o;
                }
            }
        }
    }
}

// ---------------- usproj via fp16 MMA (+ in-register RoPE) ----------------
__global__ void __launch_bounds__(256) usproj_mma(
    const __half* __restrict__ qr, const __half* __restrict__ kr, const __half* __restrict__ vr,
    const __half* __restrict__ qUh, const __half* __restrict__ kUh, const __half* __restrict__ vUh,
    __half* __restrict__ qb, __half* __restrict__ kb, __half* __restrict__ vb,
    const float* __restrict__ rc, const float* __restrict__ rs)
{
    __shared__ __align__(16) __half As[64 * 40];
    __shared__ __align__(16) __half Bs[64 * 40];

    int y = blockIdx.y;
    const __half* in; const __half* Uh; __half* out; int heads, h, rope;
    float scale = 1.0f;
    if (y < 32)      { in = qr; Uh = qUh; out = qb; heads = 32; h = y;      rope = 1; scale = 0.125f * LOG2E; }
    else if (y < 40) { in = kr; Uh = kUh; out = kb; heads = 8;  h = y - 32; rope = 1; }
    else             { in = vr; Uh = vUh; out = vb; heads = 8;  h = y - 40; rope = 0; }

    int bt0 = blockIdx.x * 64;
    int tid = threadIdx.x;
    int ldin = heads * 32;
    int lane = tid & 31, warp = tid >> 5;
    int g = lane >> 2, tig = lane & 3;
    int t4 = lane >> 3;
    int wm = warp >> 1, wn = warp & 1;

    {
        int row = tid >> 2, c = tid & 3;
        *(uint4*)(As + row * 40 + c * 8) = *(const uint4*)(in + (size_t)(bt0 + row) * ldin + h * 32 + c * 8);
        *(uint4*)(Bs + row * 40 + c * 8) = *(const uint4*)(Uh + ((size_t)h * 64 + row) * 32 + c * 8);
    }
    __syncthreads();

    unsigned AsB = (unsigned)__cvta_generic_to_shared(As);
    unsigned BsB = (unsigned)__cvta_generic_to_shared(Bs);

    unsigned aoff[2], boff[2][2];
    {
        int rowA = wm * 16 + (lane & 7) + (t4 & 1) * 8;
        #pragma unroll
        for (int ks = 0; ks < 2; ks++)
            aoff[ks] = (unsigned)(rowA * 80 + (2 * ks + (t4 >> 1)) * 16);
        #pragma unroll
        for (int np = 0; np < 2; np++) {
            int rowB = wn * 16 + np * 32 + (lane & 7) + (t4 >> 1) * 8;
            #pragma unroll
            for (int ks = 0; ks < 2; ks++)
                boff[np][ks] = (unsigned)(rowB * 80 + (2 * ks + (t4 & 1)) * 16);
        }
    }

    float acc[4][4];
    #pragma unroll
    for (int i = 0; i < 4; i++)
        #pragma unroll
        for (int c = 0; c < 4; c++) acc[i][c] = 0.f;

    #pragma unroll
    for (int ks = 0; ks < 2; ks++) {
        unsigned af[4];
        LDSM4(af[0], af[1], af[2], af[3], AsB + aoff[ks]);
        #pragma unroll
        for (int np = 0; np < 2; np++) {
            unsigned bf[4];
            LDSM4(bf[0], bf[1], bf[2], bf[3], BsB + boff[np][ks]);
            unsigned b0[2] = { bf[0], bf[1] };
            unsigned b1[2] = { bf[2], bf[3] };
            MMA_F16(acc[np*2 + 0], af, b0);
            MMA_F16(acc[np*2 + 1], af, b1);
        }
    }

    int r0 = wm * 16 + g;
    #pragma unroll
    for (int hf = 0; hf < 2; hf++) {
        int r = r0 + hf * 8;
        int bt = bt0 + r; int bb = bt >> 10; int t = bt & 1023;
        size_t base = (((size_t)(bb * heads + h)) * Tv + t) * 64;
        #pragma unroll
        for (int ni = 0; ni < 2; ni++) {
            int col = wn * 16 + ni * 8 + 2 * tig;
            float x1a = acc[ni][hf*2 + 0],     x1b = acc[ni][hf*2 + 1];
            float x2a = acc[2 + ni][hf*2 + 0], x2b = acc[2 + ni][hf*2 + 1];
            if (rope) {
                float2 cc = *(const float2*)(rc + t * 32 + col);
                float2 sn = *(const float2*)(rs + t * 32 + col);
                float o1a = (x1a * cc.x - x2a * sn.x) * scale;
                float o1b = (x1b * cc.y - x2b * sn.y) * scale;
                float o2a = (x2a * cc.x + x1a * sn.x) * scale;
                float o2b = (x2b * cc.y + x1b * sn.y) * scale;
                *(__half2*)(out + base + col)      = __floats2half2_rn(o1a, o1b);
                *(__half2*)(out + base + col + 32) = __floats2half2_rn(o2a, o2b);
            } else {
                *(__half2*)(out + base + col)      = __floats2half2_rn(x1a, x1b);
                *(__half2*)(out + base + col + 32) = __floats2half2_rn(x2a, x2b);
            }
        }
    }
}

// ---------------- flash attention, fp16 MMA, in-register softmax (base-2), double-buffered KV ----------------
#define ATTN_SMEM 40960
__global__ void __launch_bounds__(256, 2) attn_kernel(const __half* __restrict__ q,
                                                      const __half* __restrict__ k,
                                                      const __half* __restrict__ v,
                                                      __half* __restrict__ ctx)
{
    extern __shared__ char asmem[];
    __shared__ float mrow[64], lrow[64];
    __shared__ float pmax[128], psum[128];

    unsigned sb  = (unsigned)__cvta_generic_to_shared(asmem);
    unsigned QsB = sb;

    int tid = threadIdx.x;
    int bh = blockIdx.y; int b = bh >> 5; int h = bh & 31; int hk = h >> 2;
    int q0 = blockIdx.x * 64;
    int lane = tid & 31, warp = tid >> 5;
    int g = lane >> 2, tig = lane & 3;
    int t4 = lane >> 3;
    int wq = warp >> 1;
    int wn = warp & 1;

    const __half* kb0 = k + ((size_t)(b * 8 + hk)) * Tv * 64;
    const __half* vb0 = v + ((size_t)(b * 8 + hk)) * Tv * 64;

    int cprow[2], cpc[2];
    unsigned cpoff[2];
    #pragma unroll
    for (int kk = 0; kk < 2; kk++) {
        int lin = tid + kk * 256;
        cprow[kk] = lin >> 3; cpc[kk] = lin & 7;
        cpoff[kk] = (unsigned)(cprow[kk] * 128 + ((cpc[kk] ^ (cprow[kk] & 7)) << 4));
    }

    {
        unsigned kbB = sb + 8192u, vbB = sb + 16384u;
        #pragma unroll
        for (int kk = 0; kk < 2; kk++) {
            size_t off = ((size_t)cprow[kk]) * 64 + cpc[kk] * 8;
            CP_ASYNC16(kbB + cpoff[kk], kb0 + off);
            CP_ASYNC16(vbB + cpoff[kk], vb0 + off);
        }
        CP_COMMIT();
    }

    const __half* qbase = q + (((size_t)(b * 32 + h)) * Tv + q0) * 64;
    #pragma unroll
    for (int kk = 0; kk < 2; kk++) {
        int lin = tid + kk * 256;
        int row = lin >> 3, c = lin & 7;
        uint4 u = *(const uint4*)(qbase + (size_t)row * 64 + c * 8);
        *(uint4*)(asmem + row * 128 + ((c ^ (row & 7)) << 4)) = u;
    }
    if (tid < 64) { mrow[tid] = -INFINITY; lrow[tid] = 0.f; }

    unsigned aoffQ[4], boffK[2][4], voffV[2][4];
    {
        int rowA = wq * 16 + (lane & 7) + (t4 & 1) * 8;
        #pragma unroll
        for (int ks = 0; ks < 4; ks++) {
            int ca = 2 * ks + (t4 >> 1);
            aoffQ[ks] = (unsigned)(rowA * 128 + ((ca ^ (rowA & 7)) << 4));
        }
        #pragma unroll
        for (int nb = 0; nb < 2; nb++) {
            int rowB = wn * 32 + nb * 16 + (lane & 7) + (t4 >> 1) * 8;
            #pragma unroll
            for (int ks = 0; ks < 4; ks++) {
                int cb = 2 * ks + (t4 & 1);
                boffK[nb][ks] = (unsigned)(rowB * 128 + ((cb ^ (rowB & 7)) << 4));
            }
        }
        #pragma unroll
        for (int t = 0; t < 2; t++) {
            int rowV = wn * 32 + t * 16 + (lane & 7) + (t4 & 1) * 8;
            #pragma unroll
            for (int np = 0; np < 4; np++) {
                int cv = np * 2 + (t4 >> 1);
                voffV[t][np] = (unsigned)(rowV * 128 + ((cv ^ (rowV & 7)) << 4));
            }
        }
    }

    int r0 = wq * 16 + g, r1 = r0 + 8;
    float cacc[8][4];
    #pragma unroll
    for (int ni = 0; ni < 8; ni++)
        #pragma unroll
        for (int c = 0; c < 4; c++) cacc[ni][c] = 0.f;

    int ntile = (q0 >> 6) + 1;
    for (int kt = 0; kt < ntile; kt++) {
        int buf = kt & 1;
        CP_WAIT(0);
        __syncthreads();

        if (kt + 1 < ntile) {
            unsigned kbB = sb + 8192u + (unsigned)(buf ^ 1) * 16384u;
            unsigned vbB = kbB + 8192u;
            #pragma unroll
            for (int kk = 0; kk < 2; kk++) {
                size_t off = ((size_t)((kt + 1) * 64 + cprow[kk])) * 64 + cpc[kk] * 8;
                CP_ASYNC16(kbB + cpoff[kk], kb0 + off);
                CP_ASYNC16(vbB + cpoff[kk], vb0 + off);
            }
            CP_COMMIT();
        }

        unsigned KsB = sb + 8192u + (unsigned)buf * 16384u;
        unsigned VsB = KsB + 8192u;

        float sacc[4][4] = {};
        #pragma unroll
        for (int ks = 0; ks < 4; ks++) {
            unsigned af[4];
            LDSM4(af[0], af[1], af[2], af[3], QsB + aoffQ[ks]);
            #pragma unroll
            for (int nb = 0; nb < 2; nb++) {
                unsigned bf[4];
                LDSM4(bf[0], bf[1], bf[2], bf[3], KsB + boffK[nb][ks]);
                unsigned b0[2] = { bf[0], bf[1] };
                unsigned b1[2] = { bf[2], bf[3] };
                MMA_F16(sacc[nb*2 + 0], af, b0);
                MMA_F16(sacc[nb*2 + 1], af, b1);
            }
        }

        if (kt == ntile - 1) {
            int qi0 = q0 + r0, qi1 = q0 + r1;
            #pragma unroll
            for (int ni = 0; ni < 4; ni++) {
                int kc = kt * 64 + wn * 32 + ni * 8 + 2 * tig;
                if (kc > qi0)     sacc[ni][0] = -INFINITY;
                if (kc + 1 > qi0) sacc[ni][1] = -INFINITY;
                if (kc > qi1)     sacc[ni][2] = -INFINITY;
                if (kc + 1 > qi1) sacc[ni][3] = -INFINITY;
            }
        }

        float pm0 = -INFINITY, pm1 = -INFINITY;
        #pragma unroll
        for (int ni = 0; ni < 4; ni++) {
            pm0 = fmaxf(pm0, fmaxf(sacc[ni][0], sacc[ni][1]));
            pm1 = fmaxf(pm1, fmaxf(sacc[ni][2], sacc[ni][3]));
        }
        pm0 = fmaxf(pm0, __shfl_xor_sync(0xffffffffu, pm0, 1));
        pm0 = fmaxf(pm0, __shfl_xor_sync(0xffffffffu, pm0, 2));
        pm1 = fmaxf(pm1, __shfl_xor_sync(0xffffffffu, pm1, 1));
        pm1 = fmaxf(pm1, __shfl_xor_sync(0xffffffffu, pm1, 2));
        if (tig == 0) { pmax[wn * 64 + r0] = pm0; pmax[wn * 64 + r1] = pm1; }
        __syncthreads();

        float mo0 = mrow[r0], mo1 = mrow[r1];
        float mx0 = fmaxf(mo0, fmaxf(pmax[r0], pmax[64 + r0]));
        float mx1 = fmaxf(mo1, fmaxf(pmax[r1], pmax[64 + r1]));
        float rsc0 = ex2f(mo0 - mx0);
        float rsc1 = ex2f(mo1 - mx1);

        unsigned pf[4][2];
        float s0 = 0.f, s1 = 0.f;
        #pragma unroll
        for (int ni = 0; ni < 4; ni++) {
            float p0 = ex2f(sacc[ni][0] - mx0);
            float p1 = ex2f(sacc[ni][1] - mx0);
            float p2 = ex2f(sacc[ni][2] - mx1);
            float p3 = ex2f(sacc[ni][3] - mx1);
            s0 += p0 + p1; s1 += p2 + p3;
            __half2 h01 = __floats2half2_rn(p0, p1);
            __half2 h23 = __floats2half2_rn(p2, p3);
            pf[ni][0] = *(unsigned*)&h01;
            pf[ni][1] = *(unsigned*)&h23;
        }
        s0 += __shfl_xor_sync(0xffffffffu, s0, 1);
        s0 += __shfl_xor_sync(0xffffffffu, s0, 2);
        s1 += __shfl_xor_sync(0xffffffffu, s1, 1);
        s1 += __shfl_xor_sync(0xffffffffu, s1, 2);
        if (tig == 0) { psum[wn * 64 + r0] = s0; psum[wn * 64 + r1] = s1; }

        #pragma unroll
        for (int ni = 0; ni < 8; ni++) {
            cacc[ni][0] *= rsc0; cacc[ni][1] *= rsc0;
            cacc[ni][2] *= rsc1; cacc[ni][3] *= rsc1;
        }

        #pragma unroll
        for (int t = 0; t < 2; t++) {
            unsigned af[4] = { pf[2*t][0], pf[2*t][1], pf[2*t+1][0], pf[2*t+1][1] };
            #pragma unroll
            for (int np = 0; np < 4; np++) {
                unsigned vf[4];
                LDSM4T(vf[0], vf[1], vf[2], vf[3], VsB + voffV[t][np]);
                unsigned b0[2] = { vf[0], vf[1] };
                unsigned b1[2] = { vf[2], vf[3] };
                MMA_F16(cacc[np*2 + 0], af, b0);
                MMA_F16(cacc[np*2 + 1], af, b1);
            }
        }
        __syncthreads();

        if (wn == 0 && tig == 0) {
            lrow[r0] = lrow[r0] * rsc0 + psum[r0] + psum[64 + r0];
            lrow[r1] = lrow[r1] * rsc1 + psum[r1] + psum[64 + r1];
            mrow[r0] = mx0;
            mrow[r1] = mx1;
        }
    }
    __syncthreads();

    float* Ored = (float*)asmem;
    if (wn == 1) {
        #pragma unroll
        for (int ni = 0; ni < 8; ni++) {
            int col = ni * 8 + 2 * tig;
            *(float2*)(Ored + r0 * 68 + col) = make_float2(cacc[ni][0], cacc[ni][1]);
            *(float2*)(Ored + r1 * 68 + col) = make_float2(cacc[ni][2], cacc[ni][3]);
        }
    }
    __syncthreads();
    if (wn == 0) {
        float inv0 = 1.f / lrow[r0];
        float inv1 = 1.f / lrow[r1];
        #pragma unroll
        for (int ni = 0; ni < 8; ni++) {
            int col = ni * 8 + 2 * tig;
            float2 a0 = *(float2*)(Ored + r0 * 68 + col);
            float2 a1 = *(float2*)(Ored + r1 * 68 + col);
            __half2 o0 = __floats2half2_rn((cacc[ni][0] + a0.x) * inv0,
                                           (cacc[ni][1] + a0.y) * inv0);
            __half2 o1 = __floats2half2_rn((cacc[ni][2] + a1.x) * inv1,
                                           (cacc[ni][3] + a1.y) * inv1);
            size_t ad0 = ((size_t)(b * Tv + q0 + r0)) * Dv + h * 64 + col;
            size_t ad1 = ((size_t)(b * Tv + q0 + r1)) * Dv + h * 64 + col;
            *(__half2*)(ctx + ad0) = o0;
            *(__half2*)(ctx + ad1) = o1;
        }
    }
}

// ---------------- launch ----------------
extern "C" void kernel_launch(void* const* d_in, const int* in_sizes, int n_in,
                              void* d_out, int out_size)
{
    const float* x     = (const float*)d_in[0];
    const float* ln1_w = (const float*)d_in[1];
    const float* ln2_w = (const float*)d_in[2];
    const float* q_Us  = (const float*)d_in[3];
    const float* q_V   = (const float*)d_in[4];
    const float* k_Us  = (const float*)d_in[5];
    const float* k_V   = (const float*)d_in[6];
    const float* v_Us  = (const float*)d_in[7];
    const float* v_V   = (const float*)d_in[8];
    const float* o_Us  = (const float*)d_in[9];
    const float* o_V   = (const float*)d_in[10];
    const float* g_Usw = (const float*)d_in[11];
    const float* g_Vw  = (const float*)d_in[12];
    const float* u_Usw = (const float*)d_in[13];
    const float* u_Vw  = (const float*)d_in[14];
    const float* d_Usw = (const float*)d_in[15];
    const float* d_Vw  = (const float*)d_in[16];
    float* out = (float*)d_out;

    __half *h1, *qr, *kr, *vr, *qb, *kb, *vb, *ctx, *orr, *h2, *gr, *ur, *gg, *ff, *dr, *wts;
    __half *qUh, *kUh, *vUh;
    float *x1, *rc, *rs;
    cudaGetSymbolAddress((void**)&h1,  g_h1);
    cudaGetSymbolAddress((void**)&qr,  g_qr);
    cudaGetSymbolAddress((void**)&kr,  g_kr);
    cudaGetSymbolAddress((void**)&vr,  g_vr);
    cudaGetSymbolAddress((void**)&qb,  g_q);
    cudaGetSymbolAddress((void**)&kb,  g_k);
    cudaGetSymbolAddress((void**)&vb,  g_v);
    cudaGetSymbolAddress((void**)&ctx, g_ctx);
    cudaGetSymbolAddress((void**)&orr, g_or);
    cudaGetSymbolAddress((void**)&x1,  g_x1);
    cudaGetSymbolAddress((void**)&h2,  g_h2);
    cudaGetSymbolAddress((void**)&gr,  g_gr);
    cudaGetSymbolAddress((void**)&ur,  g_ur);
    cudaGetSymbolAddress((void**)&gg,  g_g);
    cudaGetSymbolAddress((void**)&ff,  g_ff);
    cudaGetSymbolAddress((void**)&dr,  g_dr);
    cudaGetSymbolAddress((void**)&rc,  g_ropec);
    cudaGetSymbolAddress((void**)&rs,  g_ropes);
    cudaGetSymbolAddress((void**)&wts, g_wts);
    cudaGetSymbolAddress((void**)&qUh, g_qush);
    cudaGetSymbolAddress((void**)&kUh, g_kush);
    cudaGetSymbolAddress((void**)&vUh, g_vush);

    static cudaStream_t s2 = 0;
    static cudaEvent_t evFork = 0, evJoin = 0;
    static int init_done = 0;
    if (!init_done) {
        cudaFuncSetAttribute(gemm_h, cudaFuncAttributeMaxDynamicSharedMemorySize, 147456);
        cudaFuncSetAttribute(attn_kernel, cudaFuncAttributeMaxDynamicSharedMemorySize, ATTN_SMEM);
        cudaStreamCreateWithFlags(&s2, cudaStreamNonBlocking);
        cudaEventCreateWithFlags(&evFork, cudaEventDisableTiming);
        cudaEventCreateWithFlags(&evJoin, cudaEventDisableTiming);
        init_done = 1;
    }
    const int SM = 147456;
    dim3 blk(256);

    cudaEventRecord(evFork, 0);
    cudaStreamWaitEvent(s2, evFork, 0);
    prep_mlp<<<NW2BLK, blk, 0, s2>>>(wts, o_V, o_Us, g_Vw, u_Vw, g_Usw, u_Usw, d_Vw, d_Usw);
    cudaEventRecord(evJoin, s2);

    prep_qkv<<<NW1BLK + BT + NROPE + NQUS + 2*NKUS, blk>>>(
        wts, q_V, k_V, v_V, x, ln1_w, h1, rc, rs,
        q_Us, k_Us, v_Us, qUh, kUh, vUh);

    // fused q/k/v rank projections: N segs 1024/256/256 -> (4+1+1) x 32 blocks
    gemm_h<<<dim3(6, 32), blk, SM>>>(h1, Dv, 0, nullptr,
        wts + W_QV, qr, Hv*Rv, 4,  wts + W_KV, kr, HKv*Rv, 1,  wts + W_VV, vr, HKv*Rv, 1);

    usproj_mma<<<dim3(BT/64, 48), blk>>>(qr, kr, vr, qUh, kUh, vUh, qb, kb, vb, rc, rs);

    attn_kernel<<<dim3(Tv/64, Bv*Hv), blk, ATTN_SMEM>>>(qb, kb, vb, ctx);

    cudaStreamWaitEvent(0, evJoin, 0);

    gemm_h<<<dim3(4, 32), blk, SM>>>(ctx, Dv, 0, nullptr,
        wts + W_OV, orr, ROv, 4,  nullptr, nullptr, 0, 0,  nullptr, nullptr, 0, 0);
    gemm_h<<<dim3(8, 32), blk, SM>>>(orr, ROv, 1, x,
        wts + W_OUS, x1, Dv, 8,  nullptr, nullptr, 0, 0,  nullptr, nullptr, 0, 0);

    rms_kernel<<<BT, blk>>>(x1, ln2_w, h2);

    gemm_h<<<dim3(8, 32), blk, SM>>>(h2, Dv, 0, nullptr,
        wts + W_GV, gr, RFv, 4,  wts + W_UV, ur, RFv, 4,  nullptr, nullptr, 0, 0);

    gemm_h<<<dim3(22, 32), blk, SM>>>(gr, RFv, 0, nullptr,
        wts + W_GUS, gg, Iv, 22,  nullptr, nullptr, 0, 0,  nullptr, nullptr, 0, 0);
    gemm_h<<<dim3(22, 32), blk, SM>>>(ur, RFv, 2, gg,
        wts + W_UUS, ff, Iv, 22,  nullptr, nullptr, 0, 0,  nullptr, nullptr, 0, 0);

    gemm_h<<<dim3(4, 32), blk, SM>>>(ff, Iv, 0, nullptr,
        wts + W_DV, dr, RFv, 4,  nullptr, nullptr, 0, 0,  nullptr, nullptr, 0, 0);
    gemm_h<<<dim3(8, 32), blk, SM>>>(dr, RFv, 1, x1,
        wts + W_DUS, out, Dv, 8,  nullptr, nullptr, 0, 0,  nullptr, nullptr, 0, 0);
}

// round 16
// speedup vs baseline: 1.1753x; 1.1753x over previous
#include <cuda_runtime.h>
#include <cuda_fp16.h>
#include <math.h>

// ---------------- problem constants ----------------
#define Bv   4
#define Tv   1024
#define Dv   2048
#define Hv   32
#define DHv  64
#define HKv  8
#define Rv   32
#define ROv  1024
#define RFv  1024
#define Iv   5632
#define BT   (Bv*Tv)     // 4096

// ---------------- scratch ----------------
__device__ __half g_h1 [BT*Dv];
__device__ __half g_qr [BT*(Hv*Rv)];
__device__ __half g_kr [BT*(HKv*Rv)];
__device__ __half g_vr [BT*(HKv*Rv)];
__device__ __half g_q  [Bv*Hv*Tv*DHv];
__device__ __half g_k  [Bv*HKv*Tv*DHv];
__device__ __half g_v  [Bv*HKv*Tv*DHv];
__device__ __half g_ctx[BT*Dv];
__device__ __half g_or [BT*ROv];
__device__ float  g_x1 [BT*Dv];
__device__ __half g_h2 [BT*Dv];
__device__ __half g_gr [BT*RFv];
__device__ __half g_ur [BT*RFv];
__device__ __half g_g  [BT*Iv];
__device__ __half g_ff [BT*Iv];
__device__ __half g_dr [BT*RFv];
__device__ float  g_ropec[Tv*32];
__device__ float  g_ropes[Tv*32];
__device__ __half g_qush[Hv*DHv*Rv];
__device__ __half g_kush[HKv*DHv*Rv];
__device__ __half g_vush[HKv*DHv*Rv];
// converted (half) weights, concatenated; offsets in elements
#define W_QV   0
#define W_KV   2097152
#define W_VV   2621440
#define W_OV   3145728
#define W_OUS  5242880
#define W_GV   7340032
#define W_UV   9437184
#define W_GUS  11534336
#define W_UUS  17301504
#define W_DV   23068672
#define W_DUS  28835840
#define W_TOT  30932992
#define NW1BLK (W_OV/4096)
#define NW2BLK ((W_TOT-W_OV)/4096)
#define NROPE  (Tv*32/256)
#define NQUS   (Hv*DHv*Rv/4096)
#define NKUS   (HKv*DHv*Rv/4096)
__device__ __half g_wts[W_TOT];

// ---------------- helpers ----------------
__device__ __forceinline__ uint2 pack4h(float4 v) {
    __half2 a = __floats2half2_rn(v.x, v.y);
    __half2 b = __floats2half2_rn(v.z, v.w);
    uint2 r;
    r.x = *(unsigned*)&a;
    r.y = *(unsigned*)&b;
    return r;
}
__device__ __forceinline__ float ex2f(float x) {
    float r;
    asm("ex2.approx.ftz.f32 %0, %1;" : "=f"(r) : "f"(x));
    return r;
}
#define LOG2E 1.4426950408889634f

// ---------------- prep part 1: QKV weights + rms1 + rope table + Us->half ----------------
__global__ void __launch_bounds__(256) prep_qkv(
    __half* __restrict__ dst,
    const float* __restrict__ s0, const float* __restrict__ s1, const float* __restrict__ s2,
    const float* __restrict__ x, const float* __restrict__ ln1_w, __half* __restrict__ h1,
    float* __restrict__ rc, float* __restrict__ rs,
    const float* __restrict__ qUs, const float* __restrict__ kUs, const float* __restrict__ vUs,
    __half* __restrict__ qUh, __half* __restrict__ kUh, __half* __restrict__ vUh)
{
    int bx = blockIdx.x;
    int tid = threadIdx.x;
    if (bx < NW1BLK) {
        long i = ((long)bx * 256 + tid) * 16;
        const float* src; long base;
        if (i < W_KV)      { src = s0; base = W_QV; }
        else if (i < W_VV) { src = s1; base = W_KV; }
        else               { src = s2; base = W_VV; }
        const float4* sp = (const float4*)(src + (i - base));
        float4 v0 = sp[0], v1 = sp[1], v2 = sp[2], v3 = sp[3];
        uint2 p0 = pack4h(v0), p1 = pack4h(v1), p2 = pack4h(v2), p3 = pack4h(v3);
        uint4 o0 = { p0.x, p0.y, p1.x, p1.y };
        uint4 o1 = { p2.x, p2.y, p3.x, p3.y };
        *(uint4*)(dst + i)     = o0;
        *(uint4*)(dst + i + 8) = o1;
    } else if (bx < NW1BLK + BT) {
        int row = bx - NW1BLK;
        const float4* xr = (const float4*)(x + (size_t)row * Dv);
        float4 v0 = xr[tid];
        float4 v1 = xr[tid + 256];
        float ss = v0.x*v0.x + v0.y*v0.y + v0.z*v0.z + v0.w*v0.w
                 + v1.x*v1.x + v1.y*v1.y + v1.z*v1.z + v1.w*v1.w;
        #pragma unroll
        for (int o = 16; o; o >>= 1) ss += __shfl_xor_sync(0xffffffffu, ss, o);
        __shared__ float red[8];
        if ((tid & 31) == 0) red[tid >> 5] = ss;
        __syncthreads();
        float tot = 0.f;
        #pragma unroll
        for (int i = 0; i < 8; i++) tot += red[i];
        float inv = rsqrtf(tot * (1.0f / Dv) + 1e-5f);
        const float4* wr = (const float4*)ln1_w;
        float4 w0 = wr[tid], w1 = wr[tid + 256];
        float4 o0 = { v0.x*inv*w0.x, v0.y*inv*w0.y, v0.z*inv*w0.z, v0.w*inv*w0.w };
        float4 o1 = { v1.x*inv*w1.x, v1.y*inv*w1.y, v1.z*inv*w1.z, v1.w*inv*w1.w };
        __half* orow = h1 + (size_t)row * Dv;
        *(uint2*)(orow + tid * 4)         = pack4h(o0);
        *(uint2*)(orow + (tid + 256) * 4) = pack4h(o1);
    } else if (bx < NW1BLK + BT + NROPE) {
        int idx = (bx - NW1BLK - BT) * 256 + tid;
        int t = idx >> 5, d = idx & 31;
        float invf = expf(-0.28782313662425572f * (float)d);
        float ang = (float)t * invf;
        rc[idx] = cosf(ang);
        rs[idx] = sinf(ang);
    } else {
        int ub = bx - NW1BLK - BT - NROPE;
        const float* src; __half* dh;
        long i;
        if (ub < NQUS)            { src = qUs; dh = qUh; i = ((long)ub * 256 + tid) * 16; }
        else if (ub < NQUS+NKUS)  { src = kUs; dh = kUh; i = ((long)(ub-NQUS) * 256 + tid) * 16; }
        else                      { src = vUs; dh = vUh; i = ((long)(ub-NQUS-NKUS) * 256 + tid) * 16; }
        const float4* sp = (const float4*)(src + i);
        float4 v0 = sp[0], v1 = sp[1], v2 = sp[2], v3 = sp[3];
        uint2 p0 = pack4h(v0), p1 = pack4h(v1), p2 = pack4h(v2), p3 = pack4h(v3);
        uint4 o0 = { p0.x, p0.y, p1.x, p1.y };
        uint4 o1 = { p2.x, p2.y, p3.x, p3.y };
        *(uint4*)(dh + i)     = o0;
        *(uint4*)(dh + i + 8) = o1;
    }
}

// ---------------- prep part 2: O/G/U/D weights (side stream) ----------------
__global__ void __launch_bounds__(256) prep_mlp(
    __half* __restrict__ dst,
    const float* __restrict__ s3, const float* __restrict__ s4, const float* __restrict__ s5,
    const float* __restrict__ s6, const float* __restrict__ s7, const float* __restrict__ s8,
    const float* __restrict__ s9, const float* __restrict__ s10)
{
    long i = W_OV + ((long)blockIdx.x * 256 + threadIdx.x) * 16;
    const float* src; long base;
    if (i < W_GUS) {
        if (i < W_OUS)       { src = s3; base = W_OV; }
        else if (i < W_GV)   { src = s4; base = W_OUS; }
        else if (i < W_UV)   { src = s5; base = W_GV; }
        else                 { src = s6; base = W_UV; }
    } else {
        if (i < W_UUS)       { src = s7; base = W_GUS; }
        else if (i < W_DV)   { src = s8; base = W_UUS; }
        else if (i < W_DUS)  { src = s9; base = W_DV; }
        else                 { src = s10; base = W_DUS; }
    }
    const float4* sp = (const float4*)(src + (i - base));
    float4 v0 = sp[0], v1 = sp[1], v2 = sp[2], v3 = sp[3];
    uint2 p0 = pack4h(v0), p1 = pack4h(v1), p2 = pack4h(v2), p3 = pack4h(v3);
    uint4 o0 = { p0.x, p0.y, p1.x, p1.y };
    uint4 o1 = { p2.x, p2.y, p3.x, p3.y };
    *(uint4*)(dst + i)     = o0;
    *(uint4*)(dst + i + 8) = o1;
}

// ---------------- RMSNorm (fp32 in, fp16 out) ----------------
__global__ void __launch_bounds__(256) rms_kernel(const float* __restrict__ x,
                                                  const float* __restrict__ w,
                                                  __half* __restrict__ out)
{
    int row = blockIdx.x;
    int tid = threadIdx.x;
    const float4* xr = (const float4*)(x + (size_t)row * Dv);
    float4 v0 = xr[tid];
    float4 v1 = xr[tid + 256];
    float ss = v0.x*v0.x + v0.y*v0.y + v0.z*v0.z + v0.w*v0.w
             + v1.x*v1.x + v1.y*v1.y + v1.z*v1.z + v1.w*v1.w;
    #pragma unroll
    for (int o = 16; o; o >>= 1) ss += __shfl_xor_sync(0xffffffffu, ss, o);
    __shared__ float red[8];
    if ((tid & 31) == 0) red[tid >> 5] = ss;
    __syncthreads();
    float tot = 0.f;
    #pragma unroll
    for (int i = 0; i < 8; i++) tot += red[i];
    float inv = rsqrtf(tot * (1.0f / Dv) + 1e-5f);
    const float4* wr = (const float4*)w;
    float4 w0 = wr[tid], w1 = wr[tid + 256];
    float4 o0 = { v0.x*inv*w0.x, v0.y*inv*w0.y, v0.z*inv*w0.z, v0.w*inv*w0.w };
    float4 o1 = { v1.x*inv*w1.x, v1.y*inv*w1.y, v1.z*inv*w1.z, v1.w*inv*w1.w };
    __half* orow = out + (size_t)row * Dv;
    *(uint2*)(orow + tid * 4)         = pack4h(o0);
    *(uint2*)(orow + (tid + 256) * 4) = pack4h(o1);
}

// ---------------- fp16 tensor-core GEMM (3-stage, TBK=64, ldmatrix) — R14 config ----------------
#define STAGES 3

#define CP_ASYNC16(dst, src) asm volatile("cp.async.cg.shared.global [%0], [%1], 16;\n" :: "r"(dst), "l"(src))
#define CP_COMMIT() asm volatile("cp.async.commit_group;\n" ::)
#define CP_WAIT(n)  asm volatile("cp.async.wait_group %0;\n" :: "n"(n))

#define LDSM4(r0, r1, r2, r3, addr) \
    asm volatile("ldmatrix.sync.aligned.m8n8.x4.shared.b16 {%0,%1,%2,%3}, [%4];" \
        : "=r"(r0), "=r"(r1), "=r"(r2), "=r"(r3) : "r"(addr))

#define LDSM4T(r0, r1, r2, r3, addr) \
    asm volatile("ldmatrix.sync.aligned.m8n8.x4.trans.shared.b16 {%0,%1,%2,%3}, [%4];" \
        : "=r"(r0), "=r"(r1), "=r"(r2), "=r"(r3) : "r"(addr))

#define MMA_F16(d, a, b) \
    asm volatile("mma.sync.aligned.m16n8k16.row.col.f32.f16.f16.f32 " \
        "{%0,%1,%2,%3}, {%4,%5,%6,%7}, {%8,%9}, {%0,%1,%2,%3};" \
        : "+f"(d[0]), "+f"(d[1]), "+f"(d[2]), "+f"(d[3]) \
        : "r"(a[0]), "r"(a[1]), "r"(a[2]), "r"(a[3]), "r"(b[0]), "r"(b[1]))

__global__ void __launch_bounds__(256, 2) gemm_h(
    const __half* __restrict__ A, int K, int mode, const void* __restrict__ aux,
    const __half* __restrict__ B0, void* __restrict__ C0, int N0, int nb0,
    const __half* __restrict__ B1, void* __restrict__ C1, int N1, int nb1,
    const __half* __restrict__ B2, void* __restrict__ C2, int N2, int nb2)
{
    extern __shared__ __half smem[];
    unsigned sbase = (unsigned)__cvta_generic_to_shared(smem);

    int bx = blockIdx.x;
    const __half* Bw; void* C; int N; int bnb;
    if (bx < nb0)            { Bw = B0; C = C0; N = N0; bnb = bx; }
    else if (bx < nb0 + nb1) { Bw = B1; C = C1; N = N1; bnb = bx - nb0; }
    else                     { Bw = B2; C = C2; N = N2; bnb = bx - nb0 - nb1; }

    int tid  = threadIdx.x;
    int bm = blockIdx.y * 128;
    int bn = bnb * 128;
    int lane = tid & 31, warp = tid >> 5;
    int wm = warp >> 1, wn = warp & 1;
    int g  = lane >> 2, tig = lane & 3;

    unsigned dstoff[4];
    const __half* srcA[4];
    const __half* srcB[4];
    #pragma unroll
    for (int i = 0; i < 4; i++) {
        int lin = tid + i * 256;
        int row = lin >> 3, c = lin & 7;
        dstoff[i] = (unsigned)(row * 128 + ((c ^ (row & 7)) << 4));
        srcA[i] = A  + (size_t)(bm + row) * K + c * 8;
        srcB[i] = Bw + (size_t)(bn + row) * K + c * 8;
    }

    int t4 = lane >> 3;
    unsigned aoff[2][4], boff[4][4];
    #pragma unroll
    for (int mi = 0; mi < 2; mi++) {
        int row = wm * 32 + mi * 16 + (lane & 7) + (t4 & 1) * 8;
        #pragma unroll
        for (int ks = 0; ks < 4; ks++) {
            int chunk = 2 * ks + (t4 >> 1);
            aoff[mi][ks] = (unsigned)(row * 128 + ((chunk ^ (row & 7)) << 4));
        }
    }
    #pragma unroll
    for (int np = 0; np < 4; np++) {
        int row = wn * 64 + np * 16 + (lane & 7) + (t4 >> 1) * 8;
        #pragma unroll
        for (int ks = 0; ks < 4; ks++) {
            int chunk = 2 * ks + (t4 & 1);
            boff[np][ks] = (unsigned)(row * 128 + ((chunk ^ (row & 7)) << 4));
        }
    }

    float acc[2][8][4];
    #pragma unroll
    for (int mi = 0; mi < 2; mi++)
        #pragma unroll
        for (int ni = 0; ni < 8; ni++)
            #pragma unroll
            for (int q = 0; q < 4; q++) acc[mi][ni][q] = 0.f;

    const int NT = K >> 6;

    #pragma unroll
    for (int s = 0; s < STAGES - 1; s++) {
        unsigned da = sbase + (unsigned)s * 32768u;
        unsigned db = da + 16384u;
        #pragma unroll
        for (int i = 0; i < 4; i++) {
            CP_ASYNC16(da + dstoff[i], srcA[i] + (size_t)s * 64);
            CP_ASYNC16(db + dstoff[i], srcB[i] + (size_t)s * 64);
        }
        CP_COMMIT();
    }

    for (int kt = 0; kt < NT; kt++) {
        int st = kt % STAGES;
        CP_WAIT(STAGES - 2);
        __syncthreads();

        int pf = kt + STAGES - 1;
        if (pf < NT) {
            int pst = pf % STAGES;
            unsigned da = sbase + (unsigned)pst * 32768u;
            unsigned db = da + 16384u;
            #pragma unroll
            for (int i = 0; i < 4; i++) {
                CP_ASYNC16(da + dstoff[i], srcA[i] + (size_t)pf * 64);
                CP_ASYNC16(db + dstoff[i], srcB[i] + (size_t)pf * 64);
            }
        }
        CP_COMMIT();

        unsigned AsB = sbase + (unsigned)st * 32768u;
        unsigned BsB = AsB + 16384u;

        #pragma unroll
        for (int ks = 0; ks < 4; ks++) {
            unsigned af[2][4];
            LDSM4(af[0][0], af[0][1], af[0][2], af[0][3], AsB + aoff[0][ks]);
            LDSM4(af[1][0], af[1][1], af[1][2], af[1][3], AsB + aoff[1][ks]);
            unsigned bf[8][2];
            #pragma unroll
            for (int np = 0; np < 4; np++)
                LDSM4(bf[2*np][0], bf[2*np][1], bf[2*np+1][0], bf[2*np+1][1],
                      BsB + boff[np][ks]);
            #pragma unroll
            for (int mi = 0; mi < 2; mi++)
                #pragma unroll
                for (int ni = 0; ni < 8; ni++)
                    MMA_F16(acc[mi][ni], af[mi], bf[ni]);
        }
    }

    #pragma unroll
    for (int mi = 0; mi < 2; mi++) {
        int row0 = bm + wm * 32 + mi * 16 + g;
        #pragma unroll
        for (int half = 0; half < 2; half++) {
            int row = row0 + half * 8;
            size_t rowoff = (size_t)row * N;
            #pragma unroll
            for (int ni = 0; ni < 8; ni++) {
                int col = bn + wn * 64 + ni * 8 + 2 * tig;
                size_t idx = rowoff + col;
                float vx = acc[mi][ni][half * 2 + 0];
                float vy = acc[mi][ni][half * 2 + 1];
                if (mode == 1) {
                    float2 rsd = *(const float2*)((const float*)aux + idx);
                    vx += rsd.x; vy += rsd.y;
                    float2 o = { vx, vy };
                    *(float2*)((float*)C + idx) = o;
                } else {
                    if (mode == 2) {
                        __half2 gh = *(const __half2*)((const __half*)aux + idx);
                        float2 gf = __half22float2(gh);
                        vx *= gf.x / (1.f + __expf(-gf.x));
                        vy *= gf.y / (1.f + __expf(-gf.y));
                    }
                    __half2 o = __floats2half2_rn(vx, vy);
                    *(__half2*)((__half*)C + idx) = o;
                }
            }
        }
    }
}

// ---------------- usproj via fp16 MMA (+ in-register RoPE) ----------------
__global__ void __launch_bounds__(256) usproj_mma(
    const __half* __restrict__ qr, const __half* __restrict__ kr, const __half* __restrict__ vr,
    const __half* __restrict__ qUh, const __half* __restrict__ kUh, const __half* __restrict__ vUh,
    __half* __restrict__ qb, __half* __restrict__ kb, __half* __restrict__ vb,
    const float* __restrict__ rc, const float* __restrict__ rs)
{
    __shared__ __align__(16) __half As[64 * 40];
    __shared__ __align__(16) __half Bs[64 * 40];

    int y = blockIdx.y;
    const __half* in; const __half* Uh; __half* out; int heads, h, rope;
    float scale = 1.0f;
    if (y < 32)      { in = qr; Uh = qUh; out = qb; heads = 32; h = y;      rope = 1; scale = 0.125f * LOG2E; }
    else if (y < 40) { in = kr; Uh = kUh; out = kb; heads = 8;  h = y - 32; rope = 1; }
    else             { in = vr; Uh = vUh; out = vb; heads = 8;  h = y - 40; rope = 0; }

    int bt0 = blockIdx.x * 64;
    int tid = threadIdx.x;
    int ldin = heads * 32;
    int lane = tid & 31, warp = tid >> 5;
    int g = lane >> 2, tig = lane & 3;
    int t4 = lane >> 3;
    int wm = warp >> 1, wn = warp & 1;

    {
        int row = tid >> 2, c = tid & 3;
        *(uint4*)(As + row * 40 + c * 8) = *(const uint4*)(in + (size_t)(bt0 + row) * ldin + h * 32 + c * 8);
        *(uint4*)(Bs + row * 40 + c * 8) = *(const uint4*)(Uh + ((size_t)h * 64 + row) * 32 + c * 8);
    }
    __syncthreads();

    unsigned AsB = (unsigned)__cvta_generic_to_shared(As);
    unsigned BsB = (unsigned)__cvta_generic_to_shared(Bs);

    unsigned aoff[2], boff[2][2];
    {
        int rowA = wm * 16 + (lane & 7) + (t4 & 1) * 8;
        #pragma unroll
        for (int ks = 0; ks < 2; ks++)
            aoff[ks] = (unsigned)(rowA * 80 + (2 * ks + (t4 >> 1)) * 16);
        #pragma unroll
        for (int np = 0; np < 2; np++) {
            int rowB = wn * 16 + np * 32 + (lane & 7) + (t4 >> 1) * 8;
            #pragma unroll
            for (int ks = 0; ks < 2; ks++)
                boff[np][ks] = (unsigned)(rowB * 80 + (2 * ks + (t4 & 1)) * 16);
        }
    }

    float acc[4][4];
    #pragma unroll
    for (int i = 0; i < 4; i++)
        #pragma unroll
        for (int c = 0; c < 4; c++) acc[i][c] = 0.f;

    #pragma unroll
    for (int ks = 0; ks < 2; ks++) {
        unsigned af[4];
        LDSM4(af[0], af[1], af[2], af[3], AsB + aoff[ks]);
        #pragma unroll
        for (int np = 0; np < 2; np++) {
            unsigned bf[4];
            LDSM4(bf[0], bf[1], bf[2], bf[3], BsB + boff[np][ks]);
            unsigned b0[2] = { bf[0], bf[1] };
            unsigned b1[2] = { bf[2], bf[3] };
            MMA_F16(acc[np*2 + 0], af, b0);
            MMA_F16(acc[np*2 + 1], af, b1);
        }
    }

    int r0 = wm * 16 + g;
    #pragma unroll
    for (int hf = 0; hf < 2; hf++) {
        int r = r0 + hf * 8;
        int bt = bt0 + r; int bb = bt >> 10; int t = bt & 1023;
        size_t base = (((size_t)(bb * heads + h)) * Tv + t) * 64;
        #pragma unroll
        for (int ni = 0; ni < 2; ni++) {
            int col = wn * 16 + ni * 8 + 2 * tig;
            float x1a = acc[ni][hf*2 + 0],     x1b = acc[ni][hf*2 + 1];
            float x2a = acc[2 + ni][hf*2 + 0], x2b = acc[2 + ni][hf*2 + 1];
            if (rope) {
                float2 cc = *(const float2*)(rc + t * 32 + col);
                float2 sn = *(const float2*)(rs + t * 32 + col);
                float o1a = (x1a * cc.x - x2a * sn.x) * scale;
                float o1b = (x1b * cc.y - x2b * sn.y) * scale;
                float o2a = (x2a * cc.x + x1a * sn.x) * scale;
                float o2b = (x2b * cc.y + x1b * sn.y) * scale;
                *(__half2*)(out + base + col)      = __floats2half2_rn(o1a, o1b);
                *(__half2*)(out + base + col + 32) = __floats2half2_rn(o2a, o2b);
            } else {
                *(__half2*)(out + base + col)      = __floats2half2_rn(x1a, x1b);
                *(__half2*)(out + base + col + 32) = __floats2half2_rn(x2a, x2b);
            }
        }
    }
}

// ---------------- flash attention: fp16 MMA, register softmax state, 2 syncs/tile ----------------
#define ATTN_SMEM 40960
__global__ void __launch_bounds__(256, 2) attn_kernel(const __half* __restrict__ q,
                                                      const __half* __restrict__ k,
                                                      const __half* __restrict__ v,
                                                      __half* __restrict__ ctx)
{
    extern __shared__ char asmem[];
    __shared__ float pmax[128];    // [wn][row]

    unsigned sb  = (unsigned)__cvta_generic_to_shared(asmem);
    unsigned QsB = sb;

    int tid = threadIdx.x;
    int bh = blockIdx.y; int b = bh >> 5; int h = bh & 31; int hk = h >> 2;
    int q0 = blockIdx.x * 64;
    int lane = tid & 31, warp = tid >> 5;
    int g = lane >> 2, tig = lane & 3;
    int t4 = lane >> 3;
    int wq = warp >> 1;
    int wn = warp & 1;

    const __half* kb0 = k + ((size_t)(b * 8 + hk)) * Tv * 64;
    const __half* vb0 = v + ((size_t)(b * 8 + hk)) * Tv * 64;

    int cprow[2], cpc[2];
    unsigned cpoff[2];
    #pragma unroll
    for (int kk = 0; kk < 2; kk++) {
        int lin = tid + kk * 256;
        cprow[kk] = lin >> 3; cpc[kk] = lin & 7;
        cpoff[kk] = (unsigned)(cprow[kk] * 128 + ((cpc[kk] ^ (cprow[kk] & 7)) << 4));
    }

    {
        unsigned kbB = sb + 8192u, vbB = sb + 16384u;
        #pragma unroll
        for (int kk = 0; kk < 2; kk++) {
            size_t off = ((size_t)cprow[kk]) * 64 + cpc[kk] * 8;
            CP_ASYNC16(kbB + cpoff[kk], kb0 + off);
            CP_ASYNC16(vbB + cpoff[kk], vb0 + off);
        }
        CP_COMMIT();
    }

    const __half* qbase = q + (((size_t)(b * 32 + h)) * Tv + q0) * 64;
    #pragma unroll
    for (int kk = 0; kk < 2; kk++) {
        int lin = tid + kk * 256;
        int row = lin >> 3, c = lin & 7;
        uint4 u = *(const uint4*)(qbase + (size_t)row * 64 + c * 8);
        *(uint4*)(asmem + row * 128 + ((c ^ (row & 7)) << 4)) = u;
    }

    unsigned aoffQ[4], boffK[2][4], voffV[2][4];
    {
        int rowA = wq * 16 + (lane & 7) + (t4 & 1) * 8;
        #pragma unroll
        for (int ks = 0; ks < 4; ks++) {
            int ca = 2 * ks + (t4 >> 1);
            aoffQ[ks] = (unsigned)(rowA * 128 + ((ca ^ (rowA & 7)) << 4));
        }
        #pragma unroll
        for (int nb = 0; nb < 2; nb++) {
            int rowB = wn * 32 + nb * 16 + (lane & 7) + (t4 >> 1) * 8;
            #pragma unroll
            for (int ks = 0; ks < 4; ks++) {
                int cb = 2 * ks + (t4 & 1);
                boffK[nb][ks] = (unsigned)(rowB * 128 + ((cb ^ (rowB & 7)) << 4));
            }
        }
        #pragma unroll
        for (int t = 0; t < 2; t++) {
            int rowV = wn * 32 + t * 16 + (lane & 7) + (t4 & 1) * 8;
            #pragma unroll
            for (int np = 0; np < 4; np++) {
                int cv = np * 2 + (t4 >> 1);
                voffV[t][np] = (unsigned)(rowV * 128 + ((cv ^ (rowV & 7)) << 4));
            }
        }
    }

    int r0 = wq * 16 + g, r1 = r0 + 8;
    float cacc[8][4];
    #pragma unroll
    for (int ni = 0; ni < 8; ni++)
        #pragma unroll
        for (int c = 0; c < 4; c++) cacc[ni][c] = 0.f;

    // per-thread softmax state: running max (global) + running sum (this key-half only)
    float mo0 = -INFINITY, mo1 = -INFINITY;
    float l0 = 0.f, l1 = 0.f;

    int ntile = (q0 >> 6) + 1;
    for (int kt = 0; kt < ntile; kt++) {
        int buf = kt & 1;
        CP_WAIT(0);
        __syncthreads();   // KV buffer ready; also protects pmax reuse from prev iter

        if (kt + 1 < ntile) {
            unsigned kbB = sb + 8192u + (unsigned)(buf ^ 1) * 16384u;
            unsigned vbB = kbB + 8192u;
            #pragma unroll
            for (int kk = 0; kk < 2; kk++) {
                size_t off = ((size_t)((kt + 1) * 64 + cprow[kk])) * 64 + cpc[kk] * 8;
                CP_ASYNC16(kbB + cpoff[kk], kb0 + off);
                CP_ASYNC16(vbB + cpoff[kk], vb0 + off);
            }
            CP_COMMIT();
        }

        unsigned KsB = sb + 8192u + (unsigned)buf * 16384u;
        unsigned VsB = KsB + 8192u;

        // ---- S = Q K^T ----
        float sacc[4][4] = {};
        #pragma unroll
        for (int ks = 0; ks < 4; ks++) {
            unsigned af[4];
            LDSM4(af[0], af[1], af[2], af[3], QsB + aoffQ[ks]);
            #pragma unroll
            for (int nb = 0; nb < 2; nb++) {
                unsigned bf[4];
                LDSM4(bf[0], bf[1], bf[2], bf[3], KsB + boffK[nb][ks]);
                unsigned b0[2] = { bf[0], bf[1] };
                unsigned b1[2] = { bf[2], bf[3] };
                MMA_F16(sacc[nb*2 + 0], af, b0);
                MMA_F16(sacc[nb*2 + 1], af, b1);
            }
        }

        // ---- causal mask: diagonal tile only ----
        if (kt == ntile - 1) {
            int qi0 = q0 + r0, qi1 = q0 + r1;
            #pragma unroll
            for (int ni = 0; ni < 4; ni++) {
                int kc = kt * 64 + wn * 32 + ni * 8 + 2 * tig;
                if (kc > qi0)     sacc[ni][0] = -INFINITY;
                if (kc + 1 > qi0) sacc[ni][1] = -INFINITY;
                if (kc > qi1)     sacc[ni][2] = -INFINITY;
                if (kc + 1 > qi1) sacc[ni][3] = -INFINITY;
            }
        }

        // ---- partial row max; single cross-warp exchange ----
        float pm0 = -INFINITY, pm1 = -INFINITY;
        #pragma unroll
        for (int ni = 0; ni < 4; ni++) {
            pm0 = fmaxf(pm0, fmaxf(sacc[ni][0], sacc[ni][1]));
            pm1 = fmaxf(pm1, fmaxf(sacc[ni][2], sacc[ni][3]));
        }
        pm0 = fmaxf(pm0, __shfl_xor_sync(0xffffffffu, pm0, 1));
        pm0 = fmaxf(pm0, __shfl_xor_sync(0xffffffffu, pm0, 2));
        pm1 = fmaxf(pm1, __shfl_xor_sync(0xffffffffu, pm1, 1));
        pm1 = fmaxf(pm1, __shfl_xor_sync(0xffffffffu, pm1, 2));
        if (tig == 0) { pmax[wn * 64 + r0] = pm0; pmax[wn * 64 + r1] = pm1; }
        __syncthreads();

        float mx0 = fmaxf(mo0, fmaxf(pmax[r0], pmax[64 + r0]));
        float mx1 = fmaxf(mo1, fmaxf(pmax[r1], pmax[64 + r1]));
        float rsc0 = ex2f(mo0 - mx0);
        float rsc1 = ex2f(mo1 - mx1);
        mo0 = mx0; mo1 = mx1;

        // ---- exp2 + this-warp partial sums (register-resident) ----
        unsigned pf[4][2];
        float s0 = 0.f, s1 = 0.f;
        #pragma unroll
        for (int ni = 0; ni < 4; ni++) {
            float p0 = ex2f(sacc[ni][0] - mx0);
            float p1 = ex2f(sacc[ni][1] - mx0);
            float p2 = ex2f(sacc[ni][2] - mx1);
            float p3 = ex2f(sacc[ni][3] - mx1);
            s0 += p0 + p1; s1 += p2 + p3;
            __half2 h01 = __floats2half2_rn(p0, p1);
            __half2 h23 = __floats2half2_rn(p2, p3);
            pf[ni][0] = *(unsigned*)&h01;
            pf[ni][1] = *(unsigned*)&h23;
        }
        s0 += __shfl_xor_sync(0xffffffffu, s0, 1);
        s0 += __shfl_xor_sync(0xffffffffu, s0, 2);
        s1 += __shfl_xor_sync(0xffffffffu, s1, 1);
        s1 += __shfl_xor_sync(0xffffffffu, s1, 2);
        l0 = l0 * rsc0 + s0;
        l1 = l1 * rsc1 + s1;

        // ---- rescale accumulated O ----
        #pragma unroll
        for (int ni = 0; ni < 8; ni++) {
            cacc[ni][0] *= rsc0; cacc[ni][1] *= rsc0;
            cacc[ni][2] *= rsc1; cacc[ni][3] *= rsc1;
        }

        // ---- P V (own 32 keys, all 64 d-cols) ----
        #pragma unroll
        for (int t = 0; t < 2; t++) {
            unsigned af[4] = { pf[2*t][0], pf[2*t][1], pf[2*t+1][0], pf[2*t+1][1] };
            #pragma unroll
            for (int np = 0; np < 4; np++) {
                unsigned vf[4];
                LDSM4T(vf[0], vf[1], vf[2], vf[3], VsB + voffV[t][np]);
                unsigned b0[2] = { vf[0], vf[1] };
                unsigned b1[2] = { vf[2], vf[3] };
                MMA_F16(cacc[np*2 + 0], af, b0);
                MMA_F16(cacc[np*2 + 1], af, b1);
            }
        }
        // no third sync: next iteration's top sync covers buffer + pmax hazards
    }
    __syncthreads();

    // ---- cross-warp O + l reduce, epilogue ----
    float* Ored = (float*)asmem;   // 64 x 68 fp32 over dead Qs/K0
    if (wn == 1) {
        #pragma unroll
        for (int ni = 0; ni < 8; ni++) {
            int col = ni * 8 + 2 * tig;
            *(float2*)(Ored + r0 * 68 + col) = make_float2(cacc[ni][0], cacc[ni][1]);
            *(float2*)(Ored + r1 * 68 + col) = make_float2(cacc[ni][2], cacc[ni][3]);
        }
        if (tig == 0) { pmax[64 + r0] = l0; pmax[64 + r1] = l1; }
    }
    __syncthreads();
    if (wn == 0) {
        float inv0 = 1.f / (l0 + pmax[64 + r0]);
        float inv1 = 1.f / (l1 + pmax[64 + r1]);
        #pragma unroll
        for (int ni = 0; ni < 8; ni++) {
            int col = ni * 8 + 2 * tig;
            float2 a0 = *(float2*)(Ored + r0 * 68 + col);
            float2 a1 = *(float2*)(Ored + r1 * 68 + col);
            __half2 o0 = __floats2half2_rn((cacc[ni][0] + a0.x) * inv0,
                                           (cacc[ni][1] + a0.y) * inv0);
            __half2 o1 = __floats2half2_rn((cacc[ni][2] + a1.x) * inv1,
                                           (cacc[ni][3] + a1.y) * inv1);
            size_t ad0 = ((size_t)(b * Tv + q0 + r0)) * Dv + h * 64 + col;
            size_t ad1 = ((size_t)(b * Tv + q0 + r1)) * Dv + h * 64 + col;
            *(__half2*)(ctx + ad0) = o0;
            *(__half2*)(ctx + ad1) = o1;
        }
    }
}

// ---------------- launch ----------------
extern "C" void kernel_launch(void* const* d_in, const int* in_sizes, int n_in,
                              void* d_out, int out_size)
{
    const float* x     = (const float*)d_in[0];
    const float* ln1_w = (const float*)d_in[1];
    const float* ln2_w = (const float*)d_in[2];
    const float* q_Us  = (const float*)d_in[3];
    const float* q_V   = (const float*)d_in[4];
    const float* k_Us  = (const float*)d_in[5];
    const float* k_V   = (const float*)d_in[6];
    const float* v_Us  = (const float*)d_in[7];
    const float* v_V   = (const float*)d_in[8];
    const float* o_Us  = (const float*)d_in[9];
    const float* o_V   = (const float*)d_in[10];
    const float* g_Usw = (const float*)d_in[11];
    const float* g_Vw  = (const float*)d_in[12];
    const float* u_Usw = (const float*)d_in[13];
    const float* u_Vw  = (const float*)d_in[14];
    const float* d_Usw = (const float*)d_in[15];
    const float* d_Vw  = (const float*)d_in[16];
    float* out = (float*)d_out;

    __half *h1, *qr, *kr, *vr, *qb, *kb, *vb, *ctx, *orr, *h2, *gr, *ur, *gg, *ff, *dr, *wts;
    __half *qUh, *kUh, *vUh;
    float *x1, *rc, *rs;
    cudaGetSymbolAddress((void**)&h1,  g_h1);
    cudaGetSymbolAddress((void**)&qr,  g_qr);
    cudaGetSymbolAddress((void**)&kr,  g_kr);
    cudaGetSymbolAddress((void**)&vr,  g_vr);
    cudaGetSymbolAddress((void**)&qb,  g_q);
    cudaGetSymbolAddress((void**)&kb,  g_k);
    cudaGetSymbolAddress((void**)&vb,  g_v);
    cudaGetSymbolAddress((void**)&ctx, g_ctx);
    cudaGetSymbolAddress((void**)&orr, g_or);
    cudaGetSymbolAddress((void**)&x1,  g_x1);
    cudaGetSymbolAddress((void**)&h2,  g_h2);
    cudaGetSymbolAddress((void**)&gr,  g_gr);
    cudaGetSymbolAddress((void**)&ur,  g_ur);
    cudaGetSymbolAddress((void**)&gg,  g_g);
    cudaGetSymbolAddress((void**)&ff,  g_ff);
    cudaGetSymbolAddress((void**)&dr,  g_dr);
    cudaGetSymbolAddress((void**)&rc,  g_ropec);
    cudaGetSymbolAddress((void**)&rs,  g_ropes);
    cudaGetSymbolAddress((void**)&wts, g_wts);
    cudaGetSymbolAddress((void**)&qUh, g_qush);
    cudaGetSymbolAddress((void**)&kUh, g_kush);
    cudaGetSymbolAddress((void**)&vUh, g_vush);

    static cudaStream_t s2 = 0;
    static cudaEvent_t evFork = 0, evJoin = 0;
    static int init_done = 0;
    if (!init_done) {
        cudaFuncSetAttribute(gemm_h, cudaFuncAttributeMaxDynamicSharedMemorySize, 98304);
        cudaFuncSetAttribute(attn_kernel, cudaFuncAttributeMaxDynamicSharedMemorySize, ATTN_SMEM);
        cudaStreamCreateWithFlags(&s2, cudaStreamNonBlocking);
        cudaEventCreateWithFlags(&evFork, cudaEventDisableTiming);
        cudaEventCreateWithFlags(&evJoin, cudaEventDisableTiming);
        init_done = 1;
    }
    const int SM = 98304;
    dim3 blk(256);

    cudaEventRecord(evFork, 0);
    cudaStreamWaitEvent(s2, evFork, 0);
    prep_mlp<<<NW2BLK, blk, 0, s2>>>(wts, o_V, o_Us, g_Vw, u_Vw, g_Usw, u_Usw, d_Vw, d_Usw);
    cudaEventRecord(evJoin, s2);

    prep_qkv<<<NW1BLK + BT + NROPE + NQUS + 2*NKUS, blk>>>(
        wts, q_V, k_V, v_V, x, ln1_w, h1, rc, rs,
        q_Us, k_Us, v_Us, qUh, kUh, vUh);

    gemm_h<<<dim3(12, 32), blk, SM>>>(h1, Dv, 0, nullptr,
        wts + W_QV, qr, Hv*Rv, 8,  wts + W_KV, kr, HKv*Rv, 2,  wts + W_VV, vr, HKv*Rv, 2);

    usproj_mma<<<dim3(BT/64, 48), blk>>>(qr, kr, vr, qUh, kUh, vUh, qb, kb, vb, rc, rs);

    attn_kernel<<<dim3(Tv/64, Bv*Hv), blk, ATTN_SMEM>>>(qb, kb, vb, ctx);

    cudaStreamWaitEvent(0, evJoin, 0);

    gemm_h<<<dim3(8, 32), blk, SM>>>(ctx, Dv, 0, nullptr,
        wts + W_OV, orr, ROv, 8,  nullptr, nullptr, 0, 0,  nullptr, nullptr, 0, 0);
    gemm_h<<<dim3(16, 32), blk, SM>>>(orr, ROv, 1, x,
        wts + W_OUS, x1, Dv, 16,  nullptr, nullptr, 0, 0,  nullptr, nullptr, 0, 0);

    rms_kernel<<<BT, blk>>>(x1, ln2_w, h2);

    gemm_h<<<dim3(16, 32), blk, SM>>>(h2, Dv, 0, nullptr,
        wts + W_GV, gr, RFv, 8,  wts + W_UV, ur, RFv, 8,  nullptr, nullptr, 0, 0);

    gemm_h<<<dim3(44, 32), blk, SM>>>(gr, RFv, 0, nullptr,
        wts + W_GUS, gg, Iv, 44,  nullptr, nullptr, 0, 0,  nullptr, nullptr, 0, 0);
    gemm_h<<<dim3(44, 32), blk, SM>>>(ur, RFv, 2, gg,
        wts + W_UUS, ff, Iv, 44,  nullptr, nullptr, 0, 0,  nullptr, nullptr, 0, 0);

    gemm_h<<<dim3(8, 32), blk, SM>>>(ff, Iv, 0, nullptr,
        wts + W_DV, dr, RFv, 8,  nullptr, nullptr, 0, 0,  nullptr, nullptr, 0, 0);
    gemm_h<<<dim3(16, 32), blk, SM>>>(dr, RFv, 1, x1,
        wts + W_DUS, out, Dv, 16,  nullptr, nullptr, 0, 0,  nullptr, nullptr, 0, 0);
}

// round 17
// speedup vs baseline: 1.1772x; 1.0016x over previous
#include <cuda_runtime.h>
#include <cuda_fp16.h>
#include <math.h>

// ---------------- problem constants ----------------
#define Bv   4
#define Tv   1024
#define Dv   2048
#define Hv   32
#define DHv  64
#define HKv  8
#define Rv   32
#define ROv  1024
#define RFv  1024
#define Iv   5632
#define BT   (Bv*Tv)     // 4096

// ---------------- scratch ----------------
__device__ __half g_h1 [BT*Dv];
__device__ __half g_qr [BT*(Hv*Rv)];
__device__ __half g_kr [BT*(HKv*Rv)];
__device__ __half g_vr [BT*(HKv*Rv)];
__device__ __half g_q  [Bv*Hv*Tv*DHv];
__device__ __half g_k  [Bv*HKv*Tv*DHv];
__device__ __half g_v  [Bv*HKv*Tv*DHv];
__device__ __half g_ctx[BT*Dv];
__device__ __half g_or [BT*ROv];
__device__ float  g_x1 [BT*Dv];
__device__ __half g_h2 [BT*Dv];
__device__ __half g_gr [BT*RFv];
__device__ __half g_ur [BT*RFv];
__device__ __half g_g  [BT*Iv];
__device__ __half g_ff [BT*Iv];
__device__ __half g_dr [BT*RFv];
__device__ float  g_ropec[Tv*32];
__device__ float  g_ropes[Tv*32];
__device__ __half g_qush[Hv*DHv*Rv];
__device__ __half g_kush[HKv*DHv*Rv];
__device__ __half g_vush[HKv*DHv*Rv];
// converted (half) weights, concatenated; offsets in elements
#define W_QV   0
#define W_KV   2097152
#define W_VV   2621440
#define W_OV   3145728
#define W_OUS  5242880
#define W_GV   7340032
#define W_UV   9437184
#define W_GUS  11534336
#define W_UUS  17301504
#define W_DV   23068672
#define W_DUS  28835840
#define W_TOT  30932992
#define NW1BLK (W_OV/4096)
#define NW2BLK ((W_TOT-W_OV)/4096)
#define NROPE  (Tv*32/256)
#define NQUS   (Hv*DHv*Rv/4096)
#define NKUS   (HKv*DHv*Rv/4096)
__device__ __half g_wts[W_TOT];

// ---------------- helpers ----------------
__device__ __forceinline__ uint2 pack4h(float4 v) {
    __half2 a = __floats2half2_rn(v.x, v.y);
    __half2 b = __floats2half2_rn(v.z, v.w);
    uint2 r;
    r.x = *(unsigned*)&a;
    r.y = *(unsigned*)&b;
    return r;
}
__device__ __forceinline__ float ex2f(float x) {
    float r;
    asm("ex2.approx.ftz.f32 %0, %1;" : "=f"(r) : "f"(x));
    return r;
}
#define LOG2E 1.4426950408889634f

// ---------------- prep part 1: QKV weights + rms1 + rope table + Us->half ----------------
__global__ void __launch_bounds__(256) prep_qkv(
    __half* __restrict__ dst,
    const float* __restrict__ s0, const float* __restrict__ s1, const float* __restrict__ s2,
    const float* __restrict__ x, const float* __restrict__ ln1_w, __half* __restrict__ h1,
    float* __restrict__ rc, float* __restrict__ rs,
    const float* __restrict__ qUs, const float* __restrict__ kUs, const float* __restrict__ vUs,
    __half* __restrict__ qUh, __half* __restrict__ kUh, __half* __restrict__ vUh)
{
    int bx = blockIdx.x;
    int tid = threadIdx.x;
    if (bx < NW1BLK) {
        long i = ((long)bx * 256 + tid) * 16;
        const float* src; long base;
        if (i < W_KV)      { src = s0; base = W_QV; }
        else if (i < W_VV) { src = s1; base = W_KV; }
        else               { src = s2; base = W_VV; }
        const float4* sp = (const float4*)(src + (i - base));
        float4 v0 = sp[0], v1 = sp[1], v2 = sp[2], v3 = sp[3];
        uint2 p0 = pack4h(v0), p1 = pack4h(v1), p2 = pack4h(v2), p3 = pack4h(v3);
        uint4 o0 = { p0.x, p0.y, p1.x, p1.y };
        uint4 o1 = { p2.x, p2.y, p3.x, p3.y };
        *(uint4*)(dst + i)     = o0;
        *(uint4*)(dst + i + 8) = o1;
    } else if (bx < NW1BLK + BT) {
        int row = bx - NW1BLK;
        const float4* xr = (const float4*)(x + (size_t)row * Dv);
        float4 v0 = xr[tid];
        float4 v1 = xr[tid + 256];
        float ss = v0.x*v0.x + v0.y*v0.y + v0.z*v0.z + v0.w*v0.w
                 + v1.x*v1.x + v1.y*v1.y + v1.z*v1.z + v1.w*v1.w;
        #pragma unroll
        for (int o = 16; o; o >>= 1) ss += __shfl_xor_sync(0xffffffffu, ss, o);
        __shared__ float red[8];
        if ((tid & 31) == 0) red[tid >> 5] = ss;
        __syncthreads();
        float tot = 0.f;
        #pragma unroll
        for (int i = 0; i < 8; i++) tot += red[i];
        float inv = rsqrtf(tot * (1.0f / Dv) + 1e-5f);
        const float4* wr = (const float4*)ln1_w;
        float4 w0 = wr[tid], w1 = wr[tid + 256];
        float4 o0 = { v0.x*inv*w0.x, v0.y*inv*w0.y, v0.z*inv*w0.z, v0.w*inv*w0.w };
        float4 o1 = { v1.x*inv*w1.x, v1.y*inv*w1.y, v1.z*inv*w1.z, v1.w*inv*w1.w };
        __half* orow = h1 + (size_t)row * Dv;
        *(uint2*)(orow + tid * 4)         = pack4h(o0);
        *(uint2*)(orow + (tid + 256) * 4) = pack4h(o1);
    } else if (bx < NW1BLK + BT + NROPE) {
        int idx = (bx - NW1BLK - BT) * 256 + tid;
        int t = idx >> 5, d = idx & 31;
        float invf = expf(-0.28782313662425572f * (float)d);
        float ang = (float)t * invf;
        rc[idx] = cosf(ang);
        rs[idx] = sinf(ang);
    } else {
        int ub = bx - NW1BLK - BT - NROPE;
        const float* src; __half* dh;
        long i;
        if (ub < NQUS)            { src = qUs; dh = qUh; i = ((long)ub * 256 + tid) * 16; }
        else if (ub < NQUS+NKUS)  { src = kUs; dh = kUh; i = ((long)(ub-NQUS) * 256 + tid) * 16; }
        else                      { src = vUs; dh = vUh; i = ((long)(ub-NQUS-NKUS) * 256 + tid) * 16; }
        const float4* sp = (const float4*)(src + i);
        float4 v0 = sp[0], v1 = sp[1], v2 = sp[2], v3 = sp[3];
        uint2 p0 = pack4h(v0), p1 = pack4h(v1), p2 = pack4h(v2), p3 = pack4h(v3);
        uint4 o0 = { p0.x, p0.y, p1.x, p1.y };
        uint4 o1 = { p2.x, p2.y, p3.x, p3.y };
        *(uint4*)(dh + i)     = o0;
        *(uint4*)(dh + i + 8) = o1;
    }
}

// ---------------- prep part 2: O/G/U/D weights (side stream) ----------------
__global__ void __launch_bounds__(256) prep_mlp(
    __half* __restrict__ dst,
    const float* __restrict__ s3, const float* __restrict__ s4, const float* __restrict__ s5,
    const float* __restrict__ s6, const float* __restrict__ s7, const float* __restrict__ s8,
    const float* __restrict__ s9, const float* __restrict__ s10)
{
    long i = W_OV + ((long)blockIdx.x * 256 + threadIdx.x) * 16;
    const float* src; long base;
    if (i < W_GUS) {
        if (i < W_OUS)       { src = s3; base = W_OV; }
        else if (i < W_GV)   { src = s4; base = W_OUS; }
        else if (i < W_UV)   { src = s5; base = W_GV; }
        else                 { src = s6; base = W_UV; }
    } else {
        if (i < W_UUS)       { src = s7; base = W_GUS; }
        else if (i < W_DV)   { src = s8; base = W_UUS; }
        else if (i < W_DUS)  { src = s9; base = W_DV; }
        else                 { src = s10; base = W_DUS; }
    }
    const float4* sp = (const float4*)(src + (i - base));
    float4 v0 = sp[0], v1 = sp[1], v2 = sp[2], v3 = sp[3];
    uint2 p0 = pack4h(v0), p1 = pack4h(v1), p2 = pack4h(v2), p3 = pack4h(v3);
    uint4 o0 = { p0.x, p0.y, p1.x, p1.y };
    uint4 o1 = { p2.x, p2.y, p3.x, p3.y };
    *(uint4*)(dst + i)     = o0;
    *(uint4*)(dst + i + 8) = o1;
}

// ---------------- RMSNorm (fp32 in, fp16 out) ----------------
__global__ void __launch_bounds__(256) rms_kernel(const float* __restrict__ x,
                                                  const float* __restrict__ w,
                                                  __half* __restrict__ out)
{
    int row = blockIdx.x;
    int tid = threadIdx.x;
    const float4* xr = (const float4*)(x + (size_t)row * Dv);
    float4 v0 = xr[tid];
    float4 v1 = xr[tid + 256];
    float ss = v0.x*v0.x + v0.y*v0.y + v0.z*v0.z + v0.w*v0.w
             + v1.x*v1.x + v1.y*v1.y + v1.z*v1.z + v1.w*v1.w;
    #pragma unroll
    for (int o = 16; o; o >>= 1) ss += __shfl_xor_sync(0xffffffffu, ss, o);
    __shared__ float red[8];
    if ((tid & 31) == 0) red[tid >> 5] = ss;
    __syncthreads();
    float tot = 0.f;
    #pragma unroll
    for (int i = 0; i < 8; i++) tot += red[i];
    float inv = rsqrtf(tot * (1.0f / Dv) + 1e-5f);
    const float4* wr = (const float4*)w;
    float4 w0 = wr[tid], w1 = wr[tid + 256];
    float4 o0 = { v0.x*inv*w0.x, v0.y*inv*w0.y, v0.z*inv*w0.z, v0.w*inv*w0.w };
    float4 o1 = { v1.x*inv*w1.x, v1.y*inv*w1.y, v1.z*inv*w1.z, v1.w*inv*w1.w };
    __half* orow = out + (size_t)row * Dv;
    *(uint2*)(orow + tid * 4)         = pack4h(o0);
    *(uint2*)(orow + (tid + 256) * 4) = pack4h(o1);
}

// ---------------- fp16 tensor-core GEMM (3-stage, TBK=64, ldmatrix) ----------------
#define STAGES 3

#define CP_ASYNC16(dst, src) asm volatile("cp.async.cg.shared.global [%0], [%1], 16;\n" :: "r"(dst), "l"(src))
#define CP_COMMIT() asm volatile("cp.async.commit_group;\n" ::)
#define CP_WAIT(n)  asm volatile("cp.async.wait_group %0;\n" :: "n"(n))

#define LDSM4(r0, r1, r2, r3, addr) \
    asm volatile("ldmatrix.sync.aligned.m8n8.x4.shared.b16 {%0,%1,%2,%3}, [%4];" \
        : "=r"(r0), "=r"(r1), "=r"(r2), "=r"(r3) : "r"(addr))

#define LDSM4T(r0, r1, r2, r3, addr) \
    asm volatile("ldmatrix.sync.aligned.m8n8.x4.trans.shared.b16 {%0,%1,%2,%3}, [%4];" \
        : "=r"(r0), "=r"(r1), "=r"(r2), "=r"(r3) : "r"(addr))

#define MMA_F16(d, a, b) \
    asm volatile("mma.sync.aligned.m16n8k16.row.col.f32.f16.f16.f32 " \
        "{%0,%1,%2,%3}, {%4,%5,%6,%7}, {%8,%9}, {%0,%1,%2,%3};" \
        : "+f"(d[0]), "+f"(d[1]), "+f"(d[2]), "+f"(d[3]) \
        : "r"(a[0]), "r"(a[1]), "r"(a[2]), "r"(a[3]), "r"(b[0]), "r"(b[1]))

__global__ void __launch_bounds__(256, 2) gemm_h(
    const __half* __restrict__ A, int K, int mode, const void* __restrict__ aux,
    const __half* __restrict__ B0, void* __restrict__ C0, int N0, int nb0,
    const __half* __restrict__ B1, void* __restrict__ C1, int N1, int nb1,
    const __half* __restrict__ B2, void* __restrict__ C2, int N2, int nb2)
{
    extern __shared__ __half smem[];
    unsigned sbase = (unsigned)__cvta_generic_to_shared(smem);

    int bx = blockIdx.x;
    const __half* Bw; void* C; int N; int bnb;
    if (bx < nb0)            { Bw = B0; C = C0; N = N0; bnb = bx; }
    else if (bx < nb0 + nb1) { Bw = B1; C = C1; N = N1; bnb = bx - nb0; }
    else                     { Bw = B2; C = C2; N = N2; bnb = bx - nb0 - nb1; }

    int tid  = threadIdx.x;
    int bm = blockIdx.y * 128;
    int bn = bnb * 128;
    int lane = tid & 31, warp = tid >> 5;
    int wm = warp >> 1, wn = warp & 1;
    int g  = lane >> 2, tig = lane & 3;

    unsigned dstoff[4];
    const __half* srcA[4];
    const __half* srcB[4];
    #pragma unroll
    for (int i = 0; i < 4; i++) {
        int lin = tid + i * 256;
        int row = lin >> 3, c = lin & 7;
        dstoff[i] = (unsigned)(row * 128 + ((c ^ (row & 7)) << 4));
        srcA[i] = A  + (size_t)(bm + row) * K + c * 8;
        srcB[i] = Bw + (size_t)(bn + row) * K + c * 8;
    }

    int t4 = lane >> 3;
    unsigned aoff[2][4], boff[4][4];
    #pragma unroll
    for (int mi = 0; mi < 2; mi++) {
        int row = wm * 32 + mi * 16 + (lane & 7) + (t4 & 1) * 8;
        #pragma unroll
        for (int ks = 0; ks < 4; ks++) {
            int chunk = 2 * ks + (t4 >> 1);
            aoff[mi][ks] = (unsigned)(row * 128 + ((chunk ^ (row & 7)) << 4));
        }
    }
    #pragma unroll
    for (int np = 0; np < 4; np++) {
        int row = wn * 64 + np * 16 + (lane & 7) + (t4 >> 1) * 8;
        #pragma unroll
        for (int ks = 0; ks < 4; ks++) {
            int chunk = 2 * ks + (t4 & 1);
            boff[np][ks] = (unsigned)(row * 128 + ((chunk ^ (row & 7)) << 4));
        }
    }

    float acc[2][8][4];
    #pragma unroll
    for (int mi = 0; mi < 2; mi++)
        #pragma unroll
        for (int ni = 0; ni < 8; ni++)
            #pragma unroll
            for (int q = 0; q < 4; q++) acc[mi][ni][q] = 0.f;

    const int NT = K >> 6;

    #pragma unroll
    for (int s = 0; s < STAGES - 1; s++) {
        unsigned da = sbase + (unsigned)s * 32768u;
        unsigned db = da + 16384u;
        #pragma unroll
        for (int i = 0; i < 4; i++) {
            CP_ASYNC16(da + dstoff[i], srcA[i] + (size_t)s * 64);
            CP_ASYNC16(db + dstoff[i], srcB[i] + (size_t)s * 64);
        }
        CP_COMMIT();
    }

    for (int kt = 0; kt < NT; kt++) {
        int st = kt % STAGES;
        CP_WAIT(STAGES - 2);
        __syncthreads();

        int pf = kt + STAGES - 1;
        if (pf < NT) {
            int pst = pf % STAGES;
            unsigned da = sbase + (unsigned)pst * 32768u;
            unsigned db = da + 16384u;
            #pragma unroll
            for (int i = 0; i < 4; i++) {
                CP_ASYNC16(da + dstoff[i], srcA[i] + (size_t)pf * 64);
                CP_ASYNC16(db + dstoff[i], srcB[i] + (size_t)pf * 64);
            }
        }
        CP_COMMIT();

        unsigned AsB = sbase + (unsigned)st * 32768u;
        unsigned BsB = AsB + 16384u;

        #pragma unroll
        for (int ks = 0; ks < 4; ks++) {
            unsigned af[2][4];
            LDSM4(af[0][0], af[0][1], af[0][2], af[0][3], AsB + aoff[0][ks]);
            LDSM4(af[1][0], af[1][1], af[1][2], af[1][3], AsB + aoff[1][ks]);
            unsigned bf[8][2];
            #pragma unroll
            for (int np = 0; np < 4; np++)
                LDSM4(bf[2*np][0], bf[2*np][1], bf[2*np+1][0], bf[2*np+1][1],
                      BsB + boff[np][ks]);
            #pragma unroll
            for (int mi = 0; mi < 2; mi++)
                #pragma unroll
                for (int ni = 0; ni < 8; ni++)
                    MMA_F16(acc[mi][ni], af[mi], bf[ni]);
        }
    }

    #pragma unroll
    for (int mi = 0; mi < 2; mi++) {
        int row0 = bm + wm * 32 + mi * 16 + g;
        #pragma unroll
        for (int half = 0; half < 2; half++) {
            int row = row0 + half * 8;
            size_t rowoff = (size_t)row * N;
            #pragma unroll
            for (int ni = 0; ni < 8; ni++) {
                int col = bn + wn * 64 + ni * 8 + 2 * tig;
                size_t idx = rowoff + col;
                float vx = acc[mi][ni][half * 2 + 0];
                float vy = acc[mi][ni][half * 2 + 1];
                if (mode == 1) {
                    float2 rsd = *(const float2*)((const float*)aux + idx);
                    vx += rsd.x; vy += rsd.y;
                    float2 o = { vx, vy };
                    *(float2*)((float*)C + idx) = o;
                } else {
                    if (mode == 2) {
                        __half2 gh = *(const __half2*)((const __half*)aux + idx);
                        float2 gf = __half22float2(gh);
                        vx *= gf.x / (1.f + __expf(-gf.x));
                        vy *= gf.y / (1.f + __expf(-gf.y));
                    }
                    __half2 o = __floats2half2_rn(vx, vy);
                    *(__half2*)((__half*)C + idx) = o;
                }
            }
        }
    }
}

// ---------------- usproj via fp16 MMA (+ in-register RoPE) ----------------
__global__ void __launch_bounds__(256) usproj_mma(
    const __half* __restrict__ qr, const __half* __restrict__ kr, const __half* __restrict__ vr,
    const __half* __restrict__ qUh, const __half* __restrict__ kUh, const __half* __restrict__ vUh,
    __half* __restrict__ qb, __half* __restrict__ kb, __half* __restrict__ vb,
    const float* __restrict__ rc, const float* __restrict__ rs)
{
    __shared__ __align__(16) __half As[64 * 40];
    __shared__ __align__(16) __half Bs[64 * 40];

    int y = blockIdx.y;
    const __half* in; const __half* Uh; __half* out; int heads, h, rope;
    float scale = 1.0f;
    if (y < 32)      { in = qr; Uh = qUh; out = qb; heads = 32; h = y;      rope = 1; scale = 0.125f * LOG2E; }
    else if (y < 40) { in = kr; Uh = kUh; out = kb; heads = 8;  h = y - 32; rope = 1; }
    else             { in = vr; Uh = vUh; out = vb; heads = 8;  h = y - 40; rope = 0; }

    int bt0 = blockIdx.x * 64;
    int tid = threadIdx.x;
    int ldin = heads * 32;
    int lane = tid & 31, warp = tid >> 5;
    int g = lane >> 2, tig = lane & 3;
    int t4 = lane >> 3;
    int wm = warp >> 1, wn = warp & 1;

    {
        int row = tid >> 2, c = tid & 3;
        *(uint4*)(As + row * 40 + c * 8) = *(const uint4*)(in + (size_t)(bt0 + row) * ldin + h * 32 + c * 8);
        *(uint4*)(Bs + row * 40 + c * 8) = *(const uint4*)(Uh + ((size_t)h * 64 + row) * 32 + c * 8);
    }
    __syncthreads();

    unsigned AsB = (unsigned)__cvta_generic_to_shared(As);
    unsigned BsB = (unsigned)__cvta_generic_to_shared(Bs);

    unsigned aoff[2], boff[2][2];
    {
        int rowA = wm * 16 + (lane & 7) + (t4 & 1) * 8;
        #pragma unroll
        for (int ks = 0; ks < 2; ks++)
            aoff[ks] = (unsigned)(rowA * 80 + (2 * ks + (t4 >> 1)) * 16);
        #pragma unroll
        for (int np = 0; np < 2; np++) {
            int rowB = wn * 16 + np * 32 + (lane & 7) + (t4 >> 1) * 8;
            #pragma unroll
            for (int ks = 0; ks < 2; ks++)
                boff[np][ks] = (unsigned)(rowB * 80 + (2 * ks + (t4 & 1)) * 16);
        }
    }

    float acc[4][4];
    #pragma unroll
    for (int i = 0; i < 4; i++)
        #pragma unroll
        for (int c = 0; c < 4; c++) acc[i][c] = 0.f;

    #pragma unroll
    for (int ks = 0; ks < 2; ks++) {
        unsigned af[4];
        LDSM4(af[0], af[1], af[2], af[3], AsB + aoff[ks]);
        #pragma unroll
        for (int np = 0; np < 2; np++) {
            unsigned bf[4];
            LDSM4(bf[0], bf[1], bf[2], bf[3], BsB + boff[np][ks]);
            unsigned b0[2] = { bf[0], bf[1] };
            unsigned b1[2] = { bf[2], bf[3] };
            MMA_F16(acc[np*2 + 0], af, b0);
            MMA_F16(acc[np*2 + 1], af, b1);
        }
    }

    int r0 = wm * 16 + g;
    #pragma unroll
    for (int hf = 0; hf < 2; hf++) {
        int r = r0 + hf * 8;
        int bt = bt0 + r; int bb = bt >> 10; int t = bt & 1023;
        size_t base = (((size_t)(bb * heads + h)) * Tv + t) * 64;
        #pragma unroll
        for (int ni = 0; ni < 2; ni++) {
            int col = wn * 16 + ni * 8 + 2 * tig;
            float x1a = acc[ni][hf*2 + 0],     x1b = acc[ni][hf*2 + 1];
            float x2a = acc[2 + ni][hf*2 + 0], x2b = acc[2 + ni][hf*2 + 1];
            if (rope) {
                float2 cc = *(const float2*)(rc + t * 32 + col);
                float2 sn = *(const float2*)(rs + t * 32 + col);
                float o1a = (x1a * cc.x - x2a * sn.x) * scale;
                float o1b = (x1b * cc.y - x2b * sn.y) * scale;
                float o2a = (x2a * cc.x + x1a * sn.x) * scale;
                float o2b = (x2b * cc.y + x1b * sn.y) * scale;
                *(__half2*)(out + base + col)      = __floats2half2_rn(o1a, o1b);
                *(__half2*)(out + base + col + 32) = __floats2half2_rn(o2a, o2b);
            } else {
                *(__half2*)(out + base + col)      = __floats2half2_rn(x1a, x1b);
                *(__half2*)(out + base + col + 32) = __floats2half2_rn(x2a, x2b);
            }
        }
    }
}

// ---------------- flash attention: Q fragments hoisted, register softmax, 2 syncs/tile ----------------
#define ATTN_SMEM 40960
__global__ void __launch_bounds__(256, 2) attn_kernel(const __half* __restrict__ q,
                                                      const __half* __restrict__ k,
                                                      const __half* __restrict__ v,
                                                      __half* __restrict__ ctx)
{
    extern __shared__ char asmem[];
    __shared__ float pmax[128];    // [wn][row]

    unsigned sb  = (unsigned)__cvta_generic_to_shared(asmem);
    unsigned QsB = sb;

    int tid = threadIdx.x;
    int bh = blockIdx.y; int b = bh >> 5; int h = bh & 31; int hk = h >> 2;
    int q0 = blockIdx.x * 64;
    int lane = tid & 31, warp = tid >> 5;
    int g = lane >> 2, tig = lane & 3;
    int t4 = lane >> 3;
    int wq = warp >> 1;
    int wn = warp & 1;

    const __half* kb0 = k + ((size_t)(b * 8 + hk)) * Tv * 64;
    const __half* vb0 = v + ((size_t)(b * 8 + hk)) * Tv * 64;

    int cprow[2], cpc[2];
    unsigned cpoff[2];
    #pragma unroll
    for (int kk = 0; kk < 2; kk++) {
        int lin = tid + kk * 256;
        cprow[kk] = lin >> 3; cpc[kk] = lin & 7;
        cpoff[kk] = (unsigned)(cprow[kk] * 128 + ((cpc[kk] ^ (cprow[kk] & 7)) << 4));
    }

    {
        unsigned kbB = sb + 8192u, vbB = sb + 16384u;
        #pragma unroll
        for (int kk = 0; kk < 2; kk++) {
            size_t off = ((size_t)cprow[kk]) * 64 + cpc[kk] * 8;
            CP_ASYNC16(kbB + cpoff[kk], kb0 + off);
            CP_ASYNC16(vbB + cpoff[kk], vb0 + off);
        }
        CP_COMMIT();
    }

    // stage Q, then hoist its fragments into registers (loop-invariant)
    const __half* qbase = q + (((size_t)(b * 32 + h)) * Tv + q0) * 64;
    #pragma unroll
    for (int kk = 0; kk < 2; kk++) {
        int lin = tid + kk * 256;
        int row = lin >> 3, c = lin & 7;
        uint4 u = *(const uint4*)(qbase + (size_t)row * 64 + c * 8);
        *(uint4*)(asmem + row * 128 + ((c ^ (row & 7)) << 4)) = u;
    }
    __syncthreads();

    unsigned qf[4][4];
    {
        int rowA = wq * 16 + (lane & 7) + (t4 & 1) * 8;
        #pragma unroll
        for (int ks = 0; ks < 4; ks++) {
            int ca = 2 * ks + (t4 >> 1);
            unsigned off = (unsigned)(rowA * 128 + ((ca ^ (rowA & 7)) << 4));
            LDSM4(qf[ks][0], qf[ks][1], qf[ks][2], qf[ks][3], QsB + off);
        }
    }

    unsigned boffK[2][4], voffV[2][4];
    {
        #pragma unroll
        for (int nb = 0; nb < 2; nb++) {
            int rowB = wn * 32 + nb * 16 + (lane & 7) + (t4 >> 1) * 8;
            #pragma unroll
            for (int ks = 0; ks < 4; ks++) {
                int cb = 2 * ks + (t4 & 1);
                boffK[nb][ks] = (unsigned)(rowB * 128 + ((cb ^ (rowB & 7)) << 4));
            }
        }
        #pragma unroll
        for (int t = 0; t < 2; t++) {
            int rowV = wn * 32 + t * 16 + (lane & 7) + (t4 & 1) * 8;
            #pragma unroll
            for (int np = 0; np < 4; np++) {
                int cv = np * 2 + (t4 >> 1);
                voffV[t][np] = (unsigned)(rowV * 128 + ((cv ^ (rowV & 7)) << 4));
            }
        }
    }

    int r0 = wq * 16 + g, r1 = r0 + 8;
    float cacc[8][4];
    #pragma unroll
    for (int ni = 0; ni < 8; ni++)
        #pragma unroll
        for (int c = 0; c < 4; c++) cacc[ni][c] = 0.f;

    float mo0 = -INFINITY, mo1 = -INFINITY;
    float l0 = 0.f, l1 = 0.f;

    int ntile = (q0 >> 6) + 1;
    for (int kt = 0; kt < ntile; kt++) {
        int buf = kt & 1;
        CP_WAIT(0);
        __syncthreads();

        if (kt + 1 < ntile) {
            unsigned kbB = sb + 8192u + (unsigned)(buf ^ 1) * 16384u;
            unsigned vbB = kbB + 8192u;
            #pragma unroll
            for (int kk = 0; kk < 2; kk++) {
                size_t off = ((size_t)((kt + 1) * 64 + cprow[kk])) * 64 + cpc[kk] * 8;
                CP_ASYNC16(kbB + cpoff[kk], kb0 + off);
                CP_ASYNC16(vbB + cpoff[kk], vb0 + off);
            }
            CP_COMMIT();
        }

        unsigned KsB = sb + 8192u + (unsigned)buf * 16384u;
        unsigned VsB = KsB + 8192u;

        // ---- S = Q K^T (Q from registers) ----
        float sacc[4][4] = {};
        #pragma unroll
        for (int ks = 0; ks < 4; ks++) {
            #pragma unroll
            for (int nb = 0; nb < 2; nb++) {
                unsigned bf[4];
                LDSM4(bf[0], bf[1], bf[2], bf[3], KsB + boffK[nb][ks]);
                unsigned b0[2] = { bf[0], bf[1] };
                unsigned b1[2] = { bf[2], bf[3] };
                MMA_F16(sacc[nb*2 + 0], qf[ks], b0);
                MMA_F16(sacc[nb*2 + 1], qf[ks], b1);
            }
        }

        // ---- causal mask: diagonal tile only ----
        if (kt == ntile - 1) {
            int qi0 = q0 + r0, qi1 = q0 + r1;
            #pragma unroll
            for (int ni = 0; ni < 4; ni++) {
                int kc = kt * 64 + wn * 32 + ni * 8 + 2 * tig;
                if (kc > qi0)     sacc[ni][0] = -INFINITY;
                if (kc + 1 > qi0) sacc[ni][1] = -INFINITY;
                if (kc > qi1)     sacc[ni][2] = -INFINITY;
                if (kc + 1 > qi1) sacc[ni][3] = -INFINITY;
            }
        }

        // ---- partial row max ----
        float pm0 = -INFINITY, pm1 = -INFINITY;
        #pragma unroll
        for (int ni = 0; ni < 4; ni++) {
            pm0 = fmaxf(pm0, fmaxf(sacc[ni][0], sacc[ni][1]));
            pm1 = fmaxf(pm1, fmaxf(sacc[ni][2], sacc[ni][3]));
        }
        pm0 = fmaxf(pm0, __shfl_xor_sync(0xffffffffu, pm0, 1));
        pm0 = fmaxf(pm0, __shfl_xor_sync(0xffffffffu, pm0, 2));
        pm1 = fmaxf(pm1, __shfl_xor_sync(0xffffffffu, pm1, 1));
        pm1 = fmaxf(pm1, __shfl_xor_sync(0xffffffffu, pm1, 2));
        if (tig == 0) { pmax[wn * 64 + r0] = pm0; pmax[wn * 64 + r1] = pm1; }
        __syncthreads();

        float mx0 = fmaxf(mo0, fmaxf(pmax[r0], pmax[64 + r0]));
        float mx1 = fmaxf(mo1, fmaxf(pmax[r1], pmax[64 + r1]));
        float rsc0 = ex2f(mo0 - mx0);
        float rsc1 = ex2f(mo1 - mx1);
        mo0 = mx0; mo1 = mx1;

        // ---- exp2 + this-warp partial sums ----
        unsigned pf[4][2];
        float s0 = 0.f, s1 = 0.f;
        #pragma unroll
        for (int ni = 0; ni < 4; ni++) {
            float p0 = ex2f(sacc[ni][0] - mx0);
            float p1 = ex2f(sacc[ni][1] - mx0);
            float p2 = ex2f(sacc[ni][2] - mx1);
            float p3 = ex2f(sacc[ni][3] - mx1);
            s0 += p0 + p1; s1 += p2 + p3;
            __half2 h01 = __floats2half2_rn(p0, p1);
            __half2 h23 = __floats2half2_rn(p2, p3);
            pf[ni][0] = *(unsigned*)&h01;
            pf[ni][1] = *(unsigned*)&h23;
        }
        s0 += __shfl_xor_sync(0xffffffffu, s0, 1);
        s0 += __shfl_xor_sync(0xffffffffu, s0, 2);
        s1 += __shfl_xor_sync(0xffffffffu, s1, 1);
        s1 += __shfl_xor_sync(0xffffffffu, s1, 2);
        l0 = l0 * rsc0 + s0;
        l1 = l1 * rsc1 + s1;

        // ---- rescale accumulated O ----
        #pragma unroll
        for (int ni = 0; ni < 8; ni++) {
            cacc[ni][0] *= rsc0; cacc[ni][1] *= rsc0;
            cacc[ni][2] *= rsc1; cacc[ni][3] *= rsc1;
        }

        // ---- P V ----
        #pragma unroll
        for (int t = 0; t < 2; t++) {
            unsigned af[4] = { pf[2*t][0], pf[2*t][1], pf[2*t+1][0], pf[2*t+1][1] };
            #pragma unroll
            for (int np = 0; np < 4; np++) {
                unsigned vf[4];
                LDSM4T(vf[0], vf[1], vf[2], vf[3], VsB + voffV[t][np]);
                unsigned b0[2] = { vf[0], vf[1] };
                unsigned b1[2] = { vf[2], vf[3] };
                MMA_F16(cacc[np*2 + 0], af, b0);
                MMA_F16(cacc[np*2 + 1], af, b1);
            }
        }
    }
    __syncthreads();

    // ---- cross-warp O + l reduce, epilogue ----
    float* Ored = (float*)asmem;
    if (wn == 1) {
        #pragma unroll
        for (int ni = 0; ni < 8; ni++) {
            int col = ni * 8 + 2 * tig;
            *(float2*)(Ored + r0 * 68 + col) = make_float2(cacc[ni][0], cacc[ni][1]);
            *(float2*)(Ored + r1 * 68 + col) = make_float2(cacc[ni][2], cacc[ni][3]);
        }
        if (tig == 0) { pmax[64 + r0] = l0; pmax[64 + r1] = l1; }
    }
    __syncthreads();
    if (wn == 0) {
        float inv0 = 1.f / (l0 + pmax[64 + r0]);
        float inv1 = 1.f / (l1 + pmax[64 + r1]);
        #pragma unroll
        for (int ni = 0; ni < 8; ni++) {
            int col = ni * 8 + 2 * tig;
            float2 a0 = *(float2*)(Ored + r0 * 68 + col);
            float2 a1 = *(float2*)(Ored + r1 * 68 + col);
            __half2 o0 = __floats2half2_rn((cacc[ni][0] + a0.x) * inv0,
                                           (cacc[ni][1] + a0.y) * inv0);
            __half2 o1 = __floats2half2_rn((cacc[ni][2] + a1.x) * inv1,
                                           (cacc[ni][3] + a1.y) * inv1);
            size_t ad0 = ((size_t)(b * Tv + q0 + r0)) * Dv + h * 64 + col;
            size_t ad1 = ((size_t)(b * Tv + q0 + r1)) * Dv + h * 64 + col;
            *(__half2*)(ctx + ad0) = o0;
            *(__half2*)(ctx + ad1) = o1;
        }
    }
}

// ---------------- launch ----------------
extern "C" void kernel_launch(void* const* d_in, const int* in_sizes, int n_in,
                              void* d_out, int out_size)
{
    const float* x     = (const float*)d_in[0];
    const float* ln1_w = (const float*)d_in[1];
    const float* ln2_w = (const float*)d_in[2];
    const float* q_Us  = (const float*)d_in[3];
    const float* q_V   = (const float*)d_in[4];
    const float* k_Us  = (const float*)d_in[5];
    const float* k_V   = (const float*)d_in[6];
    const float* v_Us  = (const float*)d_in[7];
    const float* v_V   = (const float*)d_in[8];
    const float* o_Us  = (const float*)d_in[9];
    const float* o_V   = (const float*)d_in[10];
    const float* g_Usw = (const float*)d_in[11];
    const float* g_Vw  = (const float*)d_in[12];
    const float* u_Usw = (const float*)d_in[13];
    const float* u_Vw  = (const float*)d_in[14];
    const float* d_Usw = (const float*)d_in[15];
    const float* d_Vw  = (const float*)d_in[16];
    float* out = (float*)d_out;

    __half *h1, *qr, *kr, *vr, *qb, *kb, *vb, *ctx, *orr, *h2, *gr, *ur, *gg, *ff, *dr, *wts;
    __half *qUh, *kUh, *vUh;
    float *x1, *rc, *rs;
    cudaGetSymbolAddress((void**)&h1,  g_h1);
    cudaGetSymbolAddress((void**)&qr,  g_qr);
    cudaGetSymbolAddress((void**)&kr,  g_kr);
    cudaGetSymbolAddress((void**)&vr,  g_vr);
    cudaGetSymbolAddress((void**)&qb,  g_q);
    cudaGetSymbolAddress((void**)&kb,  g_k);
    cudaGetSymbolAddress((void**)&vb,  g_v);
    cudaGetSymbolAddress((void**)&ctx, g_ctx);
    cudaGetSymbolAddress((void**)&orr, g_or);
    cudaGetSymbolAddress((void**)&x1,  g_x1);
    cudaGetSymbolAddress((void**)&h2,  g_h2);
    cudaGetSymbolAddress((void**)&gr,  g_gr);
    cudaGetSymbolAddress((void**)&ur,  g_ur);
    cudaGetSymbolAddress((void**)&gg,  g_g);
    cudaGetSymbolAddress((void**)&ff,  g_ff);
    cudaGetSymbolAddress((void**)&dr,  g_dr);
    cudaGetSymbolAddress((void**)&rc,  g_ropec);
    cudaGetSymbolAddress((void**)&rs,  g_ropes);
    cudaGetSymbolAddress((void**)&wts, g_wts);
    cudaGetSymbolAddress((void**)&qUh, g_qush);
    cudaGetSymbolAddress((void**)&kUh, g_kush);
    cudaGetSymbolAddress((void**)&vUh, g_vush);

    static cudaStream_t s2 = 0;
    static cudaEvent_t evFork = 0, evJoin = 0;
    static int init_done = 0;
    if (!init_done) {
        cudaFuncSetAttribute(gemm_h, cudaFuncAttributeMaxDynamicSharedMemorySize, 98304);
        cudaFuncSetAttribute(attn_kernel, cudaFuncAttributeMaxDynamicSharedMemorySize, ATTN_SMEM);
        cudaStreamCreateWithFlags(&s2, cudaStreamNonBlocking);
        cudaEventCreateWithFlags(&evFork, cudaEventDisableTiming);
        cudaEventCreateWithFlags(&evJoin, cudaEventDisableTiming);
        init_done = 1;
    }
    const int SM = 98304;
    dim3 blk(256);

    cudaEventRecord(evFork, 0);
    cudaStreamWaitEvent(s2, evFork, 0);
    prep_mlp<<<NW2BLK, blk, 0, s2>>>(wts, o_V, o_Us, g_Vw, u_Vw, g_Usw, u_Usw, d_Vw, d_Usw);
    cudaEventRecord(evJoin, s2);

    prep_qkv<<<NW1BLK + BT + NROPE + NQUS + 2*NKUS, blk>>>(
        wts, q_V, k_V, v_V, x, ln1_w, h1, rc, rs,
        q_Us, k_Us, v_Us, qUh, kUh, vUh);

    gemm_h<<<dim3(12, 32), blk, SM>>>(h1, Dv, 0, nullptr,
        wts + W_QV, qr, Hv*Rv, 8,  wts + W_KV, kr, HKv*Rv, 2,  wts + W_VV, vr, HKv*Rv, 2);

    usproj_mma<<<dim3(BT/64, 48), blk>>>(qr, kr, vr, qUh, kUh, vUh, qb, kb, vb, rc, rs);

    attn_kernel<<<dim3(Tv/64, Bv*Hv), blk, ATTN_SMEM>>>(qb, kb, vb, ctx);

    cudaStreamWaitEvent(0, evJoin, 0);

    gemm_h<<<dim3(8, 32), blk, SM>>>(ctx, Dv, 0, nullptr,
        wts + W_OV, orr, ROv, 8,  nullptr, nullptr, 0, 0,  nullptr, nullptr, 0, 0);
    gemm_h<<<dim3(16, 32), blk, SM>>>(orr, ROv, 1, x,
        wts + W_OUS, x1, Dv, 16,  nullptr, nullptr, 0, 0,  nullptr, nullptr, 0, 0);

    rms_kernel<<<BT, blk>>>(x1, ln2_w, h2);

    gemm_h<<<dim3(16, 32), blk, SM>>>(h2, Dv, 0, nullptr,
        wts + W_GV, gr, RFv, 8,  wts + W_UV, ur, RFv, 8,  nullptr, nullptr, 0, 0);

    gemm_h<<<dim3(44, 32), blk, SM>>>(gr, RFv, 0, nullptr,
        wts + W_GUS, gg, Iv, 44,  nullptr, nullptr, 0, 0,  nullptr, nullptr, 0, 0);
    gemm_h<<<dim3(44, 32), blk, SM>>>(ur, RFv, 2, gg,
        wts + W_UUS, ff, Iv, 44,  nullptr, nullptr, 0, 0,  nullptr, nullptr, 0, 0);

    gemm_h<<<dim3(8, 32), blk, SM>>>(ff, Iv, 0, nullptr,
        wts + W_DV, dr, RFv, 8,  nullptr, nullptr, 0, 0,  nullptr, nullptr, 0, 0);
    gemm_h<<<dim3(16, 32), blk, SM>>>(dr, RFv, 1, x1,
        wts + W_DUS, out, Dv, 16,  nullptr, nullptr, 0, 0,  nullptr, nullptr, 0, 0);
}